// round 3
// baseline (speedup 1.0000x reference)
#include <cuda_runtime.h>
#include <math.h>

#define TT 64
#define BB 64
#define SS 512
#define AA 16
#define RR 64
#define HH 32
#define EPSV 1e-6f

// ---------------- scratch (no allocations allowed) ----------------
__device__ float d_T[AA * SS * SS];        // transition [k][i][j]  (16.8 MB)
__device__ float d_G[SS * SS];             // gram u u^T            (1 MB)
__device__ float d_p[AA * SS];             // p[k,i] = <u_i, v_k/||v_k||>
__device__ float d_alpha_a[TT * BB * AA];  // softmax(logp_u)
__device__ float d_taupdf[HH];             // normalized poisson pmf
__device__ float d_partial[32 * BB * SS];  // GEMM k/i-split partials (4 MB)

// ---------------- helpers ----------------
__device__ __forceinline__ void fma2(unsigned long long& d, unsigned long long a,
                                     unsigned long long b) {
    asm("fma.rn.f32x2 %0, %1, %2, %0;" : "+l"(d) : "l"(a), "l"(b));
}
__device__ __forceinline__ unsigned long long pack2(float x) {
    unsigned long long r;
    unsigned int xi = __float_as_uint(x);
    asm("mov.b64 %0, {%1, %1};" : "=l"(r) : "r"(xi));
    return r;
}

// block reduce (512 threads = 16 warps), buf must have >=16 floats
__device__ __forceinline__ float bmax512(float v, float* buf) {
    int lane = threadIdx.x & 31, w = threadIdx.x >> 5;
#pragma unroll
    for (int o = 16; o; o >>= 1) v = fmaxf(v, __shfl_xor_sync(0xffffffffu, v, o));
    if (!lane) buf[w] = v;
    __syncthreads();
    if (w == 0) {
        float x = (lane < 16) ? buf[lane] : -3.402823466e38f;
#pragma unroll
        for (int o = 8; o; o >>= 1) x = fmaxf(x, __shfl_xor_sync(0xffffffffu, x, o));
        if (!lane) buf[0] = x;
    }
    __syncthreads();
    float r = buf[0];
    __syncthreads();
    return r;
}
__device__ __forceinline__ float bsum512(float v, float* buf) {
    int lane = threadIdx.x & 31, w = threadIdx.x >> 5;
#pragma unroll
    for (int o = 16; o; o >>= 1) v += __shfl_xor_sync(0xffffffffu, v, o);
    if (!lane) buf[w] = v;
    __syncthreads();
    if (w == 0) {
        float x = (lane < 16) ? buf[lane] : 0.0f;
#pragma unroll
        for (int o = 8; o; o >>= 1) x += __shfl_xor_sync(0xffffffffu, x, o);
        if (!lane) buf[0] = x;
    }
    __syncthreads();
    float r = buf[0];
    __syncthreads();
    return r;
}

// ---------------- precompute kernels ----------------
// G[i,j] = <u_i, u_j>.  grid=SS blocks, SS threads
__global__ void k_gram(const float* __restrict__ u) {
    __shared__ float ui[RR];
    int i = blockIdx.x;
    if (threadIdx.x < RR) ui[threadIdx.x] = u[i * RR + threadIdx.x];
    __syncthreads();
    int j = threadIdx.x;
    const float* uj = u + j * RR;
    float s = 0.f;
#pragma unroll
    for (int r = 0; r < RR; r++) s += ui[r] * uj[r];
    d_G[i * SS + j] = s;
}

// p[k,i].  grid=AA blocks, SS threads
__global__ void k_p(const float* __restrict__ u, const float* __restrict__ v) {
    __shared__ float vk[RR];
    __shared__ float invn;
    int k = blockIdx.x, tid = threadIdx.x;
    if (tid < RR) vk[tid] = v[k * RR + tid];
    __syncthreads();
    if (tid == 0) {
        float s = 0.f;
        for (int r = 0; r < RR; r++) s += vk[r] * vk[r];
        invn = rsqrtf(s);
    }
    __syncthreads();
    const float* ui = u + tid * RR;
    float dot = 0.f;
#pragma unroll
    for (int r = 0; r < RR; r++) dot += ui[r] * vk[r];
    d_p[k * SS + tid] = dot * invn;
}

// transition[k,i,:] = softmax_j(G[i,j] - 2 p[k,i] p[k,j]).  grid=AA*SS blocks, SS threads
__global__ void k_trans() {
    __shared__ float buf[16];
    int ki = blockIdx.x;
    int k = ki >> 9, i = ki & 511;
    int j = threadIdx.x;
    float pki = d_p[k * SS + i];
    float w = d_G[i * SS + j] - 2.0f * pki * d_p[k * SS + j];
    float m = bmax512(w, buf);
    float e = expf(w - m);
    float s = bsum512(e, buf);
    d_T[(size_t)ki * SS + j] = e / s;
}

// normalized poisson pmf over k=1..H with rate softplus(tau).  1 block, HH(=32) threads
__global__ void k_tau(const float* __restrict__ tau) {
    int h = threadIdx.x;
    float rate = log1pf(expf(tau[0]));
    float lp = (float)(h + 1) * logf(rate) - rate - lgammaf((float)(h + 2));
    float p = expf(lp);
    float s = p;
#pragma unroll
    for (int o = 16; o; o >>= 1) s += __shfl_xor_sync(0xffffffffu, s, o);
    d_taupdf[h] = p / s;
}

// alpha_a = softmax over A of logp_u.  grid=16 blocks x 256 threads, 1 row/thread
__global__ void k_alpha_a(const float* __restrict__ logp_u) {
    int row = blockIdx.x * 256 + threadIdx.x;  // < T*B = 4096
    const float* r = logp_u + row * AA;
    float m = -3.402823466e38f;
#pragma unroll
    for (int k = 0; k < AA; k++) m = fmaxf(m, r[k]);
    float e[AA], s = 0.f;
#pragma unroll
    for (int k = 0; k < AA; k++) { e[k] = expf(r[k] - m); s += e[k]; }
    float inv = 1.0f / s;
    float* o = d_alpha_a + row * AA;
#pragma unroll
    for (int k = 0; k < AA; k++) o[k] = e[k] * inv;
}

// ---------------- per-step kernel 1: GEMM partials ----------------
// grid (8 jt, 16 k, 2 iz), 128 threads.  Block computes
// partial[iz*16+k][n][jt*64 + j] = a[n,k] * sum_{i in chunk} bel[n,i] T[k,i,j]
__global__ void k_gemm(const float* __restrict__ bel, int t) {
    __shared__ float belS[64][68];
    __shared__ float Ts[64][64];
    __shared__ float a_s[64];
    const float* a_t = d_alpha_a + (size_t)t * BB * AA;

    int tid = threadIdx.x;
    int jt = blockIdx.x, k = blockIdx.y, iz = blockIdx.z;
    if (tid < 64) a_s[tid] = a_t[tid * AA + k];

    int tx = tid & 7;        // j group: j0 = tx*8
    int ty = tid >> 3;       // n group: n0 = ty*4  (16 groups)

    unsigned long long acc[4][4];
#pragma unroll
    for (int a = 0; a < 4; a++)
#pragma unroll
        for (int b = 0; b < 4; b++) acc[a][b] = 0ull;

    for (int c = 0; c < 4; c++) {
        int i0 = iz * 256 + c * 64;
#pragma unroll
        for (int l = 0; l < 32; l++) {
            int idx = l * 128 + tid;
            int n = idx >> 6, ii = idx & 63;
            belS[ii][n] = bel[n * SS + i0 + ii];
        }
#pragma unroll
        for (int l = 0; l < 32; l++) {
            int idx = l * 128 + tid;
            int ii = idx >> 6, j = idx & 63;
            Ts[ii][j] = d_T[((size_t)(k * SS + i0 + ii)) * SS + jt * 64 + j];
        }
        __syncthreads();
#pragma unroll 8
        for (int ii = 0; ii < 64; ii++) {
            float4 bq = *(const float4*)&belS[ii][ty * 4];
            ulonglong2 t01 = *(const ulonglong2*)&Ts[ii][tx * 8];
            ulonglong2 t23 = *(const ulonglong2*)&Ts[ii][tx * 8 + 4];
            const float* bf = (const float*)&bq;
#pragma unroll
            for (int n = 0; n < 4; n++) {
                unsigned long long bb = pack2(bf[n]);
                fma2(acc[n][0], bb, t01.x);
                fma2(acc[n][1], bb, t01.y);
                fma2(acc[n][2], bb, t23.x);
                fma2(acc[n][3], bb, t23.y);
            }
        }
        __syncthreads();
    }
    // epilogue: scale by a[n,k], write partials
#pragma unroll
    for (int n = 0; n < 4; n++) {
        int nn = ty * 4 + n;
        float aw = a_s[nn];
        float o[8];
#pragma unroll
        for (int m = 0; m < 4; m++) {
            float2 f = *(float2*)&acc[n][m];
            o[m * 2] = f.x * aw;
            o[m * 2 + 1] = f.y * aw;
        }
        float* op = &d_partial[((size_t)(iz * 16 + k) * 64 + nn) * SS + jt * 64 + tx * 8];
        *(float4*)op = make_float4(o[0], o[1], o[2], o[3]);
        *(float4*)(op + 4) = make_float4(o[4], o[5], o[6], o[7]);
    }
}

// ---------------- per-step kernel 2: reduce + posterior softmax + plan ----------------
// grid = 64 blocks (one per n), 512 threads
__global__ void k_step2(const float* __restrict__ lo_t, const float* __restrict__ value,
                        float* __restrict__ ab_t, float* __restrict__ api_t) {
    __shared__ float bpost[SS];
    __shared__ float lg[SS];   // logits[h*16+k], later pi*taupdf
    __shared__ float buf[16];
    int n = blockIdx.x;
    int tid = threadIdx.x;

    // phase A: s_next, posterior softmax
    float s = 0.f;
#pragma unroll
    for (int c = 0; c < 32; c++) s += d_partial[((size_t)c * 64 + n) * SS + tid];
    float val = logf(s + EPSV) + lo_t[n * SS + tid];
    float m = bmax512(val, buf);
    float e = expf(val - m);
    float sum = bsum512(e, buf);
    float b = e / sum;
    bpost[tid] = b;
    ab_t[n * SS + tid] = b;
    __syncthreads();

    // phase B: logits[h,k] = <bpost, value[h,n,k,:]> ; warp per row, 32 rows/warp
    int w = tid >> 5, lane = tid & 31;
    float4 b0 = *(const float4*)&bpost[lane * 4];
    float4 b1 = *(const float4*)&bpost[128 + lane * 4];
    float4 b2 = *(const float4*)&bpost[256 + lane * 4];
    float4 b3 = *(const float4*)&bpost[384 + lane * 4];
#pragma unroll 2
    for (int rr = 0; rr < 32; rr++) {
        int r = w * 32 + rr;
        int h = r >> 4, k = r & 15;
        const float* vp = value + ((size_t)(h * BB + n) * AA + k) * SS;
        float4 a0 = *(const float4*)(vp + lane * 4);
        float4 a1 = *(const float4*)(vp + 128 + lane * 4);
        float4 a2 = *(const float4*)(vp + 256 + lane * 4);
        float4 a3 = *(const float4*)(vp + 384 + lane * 4);
        float acc0 = a0.x * b0.x + a0.y * b0.y + a0.z * b0.z + a0.w * b0.w;
        float acc1 = a1.x * b1.x + a1.y * b1.y + a1.z * b1.z + a1.w * b1.w;
        float acc2 = a2.x * b2.x + a2.y * b2.y + a2.z * b2.z + a2.w * b2.w;
        float acc3 = a3.x * b3.x + a3.y * b3.y + a3.z * b3.z + a3.w * b3.w;
        float acc = (acc0 + acc1) + (acc2 + acc3);
#pragma unroll
        for (int o = 16; o; o >>= 1) acc += __shfl_xor_sync(0xffffffffu, acc, o);
        if (!lane) lg[r] = acc;
    }
    __syncthreads();

    // phase C: softmax over k per h, weight by taupdf, reduce over h
    if (tid < HH) {
        int h = tid;
        float mm = -3.402823466e38f;
#pragma unroll
        for (int k = 0; k < AA; k++) mm = fmaxf(mm, lg[h * AA + k]);
        float ex[AA], se = 0.f;
#pragma unroll
        for (int k = 0; k < AA; k++) { ex[k] = expf(lg[h * AA + k] - mm); se += ex[k]; }
        float tw = d_taupdf[h] / se;
#pragma unroll
        for (int k = 0; k < AA; k++) lg[h * AA + k] = ex[k] * tw;
    }
    __syncthreads();
    if (tid < AA) {
        float s2 = 0.f;
#pragma unroll
        for (int h = 0; h < HH; h++) s2 += lg[h * AA + tid];
        api_t[n * AA + tid] = s2;
    }
}

// ---------------- launch ----------------
extern "C" void kernel_launch(void* const* d_in, const int* in_sizes, int n_in,
                              void* d_out, int out_size) {
    const float* logp_o = (const float*)d_in[0];  // [T,B,S]
    const float* logp_u = (const float*)d_in[1];  // [T,B,A]
    const float* value  = (const float*)d_in[2];  // [H,B,A,S]
    const float* b      = (const float*)d_in[3];  // [B,S]
    const float* u      = (const float*)d_in[4];  // [S,R]
    const float* v      = (const float*)d_in[5];  // [A,R]
    const float* tau    = (const float*)d_in[6];  // [1,1]

    float* out = (float*)d_out;
    float* alpha_b  = out;                          // [T,B,S]
    float* alpha_pi = out + (size_t)TT * BB * SS;   // [T,B,A]

    k_gram<<<SS, SS>>>(u);
    k_p<<<AA, SS>>>(u, v);
    k_tau<<<1, HH>>>(tau);
    k_alpha_a<<<16, 256>>>(logp_u);
    k_trans<<<AA * SS, SS>>>();

    for (int t = 0; t < TT; t++) {
        const float* bel = (t == 0) ? b : (alpha_b + (size_t)(t - 1) * BB * SS);
        dim3 g1(8, 16, 2);
        k_gemm<<<g1, 128>>>(bel, t);
        k_step2<<<BB, 512>>>(logp_o + (size_t)t * BB * SS, value,
                             alpha_b + (size_t)t * BB * SS,
                             alpha_pi + (size_t)t * BB * AA);
    }
}

// round 4
// speedup vs baseline: 1.4290x; 1.4290x over previous
#include <cuda_runtime.h>
#include <math.h>

#define TT 64
#define BB 64
#define SS 512
#define AA 16
#define RR 64
#define HH 32
#define EPSV 1e-6f

// ---------------- scratch (no allocations allowed) ----------------
__device__ float d_T[AA * SS * SS];          // transition [k][i][j]  (16.8 MB)
__device__ float d_G[SS * SS];               // gram u u^T            (1 MB)
__device__ float d_p[AA * SS];               // p[k,i] = <u_i, v_k/||v_k||>
__device__ float d_alpha_a[TT * BB * AA];    // softmax(logp_u)
__device__ float d_taupdf[HH];               // normalized poisson pmf
__device__ float d_partial[64 * BB * SS];    // GEMM (iz,k)-split partials (8 MB)
__device__ float d_pi_part[8 * TT * BB * AA];// plan h-split partials (2 MB)

// ---------------- helpers ----------------
__device__ __forceinline__ void fma2(unsigned long long& d, unsigned long long a,
                                     unsigned long long b) {
    asm("fma.rn.f32x2 %0, %1, %2, %0;" : "+l"(d) : "l"(a), "l"(b));
}
__device__ __forceinline__ unsigned long long pack2(float x) {
    unsigned long long r;
    unsigned int xi = __float_as_uint(x);
    asm("mov.b64 %0, {%1, %1};" : "=l"(r) : "r"(xi));
    return r;
}

__device__ __forceinline__ float bmax512(float v, float* buf) {
    int lane = threadIdx.x & 31, w = threadIdx.x >> 5;
#pragma unroll
    for (int o = 16; o; o >>= 1) v = fmaxf(v, __shfl_xor_sync(0xffffffffu, v, o));
    if (!lane) buf[w] = v;
    __syncthreads();
    if (w == 0) {
        float x = (lane < 16) ? buf[lane] : -3.402823466e38f;
#pragma unroll
        for (int o = 8; o; o >>= 1) x = fmaxf(x, __shfl_xor_sync(0xffffffffu, x, o));
        if (!lane) buf[0] = x;
    }
    __syncthreads();
    float r = buf[0];
    __syncthreads();
    return r;
}
__device__ __forceinline__ float bsum512(float v, float* buf) {
    int lane = threadIdx.x & 31, w = threadIdx.x >> 5;
#pragma unroll
    for (int o = 16; o; o >>= 1) v += __shfl_xor_sync(0xffffffffu, v, o);
    if (!lane) buf[w] = v;
    __syncthreads();
    if (w == 0) {
        float x = (lane < 16) ? buf[lane] : 0.0f;
#pragma unroll
        for (int o = 8; o; o >>= 1) x += __shfl_xor_sync(0xffffffffu, x, o);
        if (!lane) buf[0] = x;
    }
    __syncthreads();
    float r = buf[0];
    __syncthreads();
    return r;
}

// ---------------- precompute kernels ----------------
__global__ void k_gram(const float* __restrict__ u) {
    __shared__ float ui[RR];
    int i = blockIdx.x;
    if (threadIdx.x < RR) ui[threadIdx.x] = u[i * RR + threadIdx.x];
    __syncthreads();
    int j = threadIdx.x;
    const float* uj = u + j * RR;
    float s = 0.f;
#pragma unroll
    for (int r = 0; r < RR; r++) s += ui[r] * uj[r];
    d_G[i * SS + j] = s;
}

__global__ void k_p(const float* __restrict__ u, const float* __restrict__ v) {
    __shared__ float vk[RR];
    __shared__ float invn;
    int k = blockIdx.x, tid = threadIdx.x;
    if (tid < RR) vk[tid] = v[k * RR + tid];
    __syncthreads();
    if (tid == 0) {
        float s = 0.f;
        for (int r = 0; r < RR; r++) s += vk[r] * vk[r];
        invn = rsqrtf(s);
    }
    __syncthreads();
    const float* ui = u + tid * RR;
    float dot = 0.f;
#pragma unroll
    for (int r = 0; r < RR; r++) dot += ui[r] * vk[r];
    d_p[k * SS + tid] = dot * invn;
}

__global__ void k_trans() {
    __shared__ float buf[16];
    int ki = blockIdx.x;
    int k = ki >> 9, i = ki & 511;
    int j = threadIdx.x;
    float pki = d_p[k * SS + i];
    float w = d_G[i * SS + j] - 2.0f * pki * d_p[k * SS + j];
    float m = bmax512(w, buf);
    float e = expf(w - m);
    float s = bsum512(e, buf);
    d_T[(size_t)ki * SS + j] = e / s;
}

__global__ void k_tau(const float* __restrict__ tau) {
    int h = threadIdx.x;
    float rate = log1pf(expf(tau[0]));
    float lp = (float)(h + 1) * logf(rate) - rate - lgammaf((float)(h + 2));
    float p = expf(lp);
    float s = p;
#pragma unroll
    for (int o = 16; o; o >>= 1) s += __shfl_xor_sync(0xffffffffu, s, o);
    d_taupdf[h] = p / s;
}

__global__ void k_alpha_a(const float* __restrict__ logp_u) {
    int row = blockIdx.x * 256 + threadIdx.x;  // < T*B = 4096
    const float* r = logp_u + row * AA;
    float m = -3.402823466e38f;
#pragma unroll
    for (int k = 0; k < AA; k++) m = fmaxf(m, r[k]);
    float e[AA], s = 0.f;
#pragma unroll
    for (int k = 0; k < AA; k++) { e[k] = expf(r[k] - m); s += e[k]; }
    float inv = 1.0f / s;
    float* o = d_alpha_a + row * AA;
#pragma unroll
    for (int k = 0; k < AA; k++) o[k] = e[k] * inv;
}

// ---------------- per-step kernel 1: GEMM partials ----------------
// grid (4 jt, 16 k, 4 iz), 256 threads, dynamic smem.
// partial[iz*16+k][n][jt*128 + j] = a[n,k] * sum_{i in 128-chunk} bel[n,i] T[k,i,j]
#define GEMM_SMEM (65 * 64 * 8 + 64 * 128 * 4 + 256)
__global__ void k_gemm(const float* __restrict__ bel, int t) {
    extern __shared__ char sm[];
    unsigned long long(*Bs)[65] = (unsigned long long(*)[65])sm;            // 33280 B
    float(*Ts)[128] = (float(*)[128])(sm + 65 * 64 * 8);                    // 32768 B
    float* a_s = (float*)(sm + 65 * 64 * 8 + 64 * 128 * 4);                 // 256 B

    int tid = threadIdx.x;
    int jt = blockIdx.x, k = blockIdx.y, iz = blockIdx.z;
    if (tid < 64) a_s[tid] = d_alpha_a[(size_t)t * BB * AA + tid * AA + k];

    int tx = tid & 15;   // j group: j0 = jt*128 + tx*8
    int ty = tid >> 4;   // n group: n0 = ty*4

    unsigned long long acc[4][4];
#pragma unroll
    for (int a = 0; a < 4; a++)
#pragma unroll
        for (int b = 0; b < 4; b++) acc[a][b] = 0ull;

#pragma unroll
    for (int c = 0; c < 2; c++) {
        int i0 = iz * 128 + c * 64;
        // Ts[ii][j] <- T[k][i0+ii][jt*128 + j]   (8192 floats, coalesced)
#pragma unroll
        for (int l = 0; l < 32; l++) {
            int idx = l * 256 + tid;
            int ii = idx >> 7, j = idx & 127;
            Ts[ii][j] = d_T[((size_t)(k * SS + i0 + ii)) * SS + jt * 128 + j];
        }
        // Bs[ii][n] <- {bel[n][i0+ii], bel[n][i0+ii]}  (4096 packed)
#pragma unroll
        for (int l = 0; l < 16; l++) {
            int idx = l * 256 + tid;
            int ii = idx & 63, n = idx >> 6;
            Bs[ii][n] = pack2(bel[n * SS + i0 + ii]);
        }
        __syncthreads();
#pragma unroll 8
        for (int ii = 0; ii < 64; ii++) {
            ulonglong2 t01 = *(const ulonglong2*)&Ts[ii][tx * 8];
            ulonglong2 t23 = *(const ulonglong2*)&Ts[ii][tx * 8 + 4];
#pragma unroll
            for (int nn = 0; nn < 4; nn++) {
                unsigned long long bb = Bs[ii][ty * 4 + nn];
                fma2(acc[nn][0], bb, t01.x);
                fma2(acc[nn][1], bb, t01.y);
                fma2(acc[nn][2], bb, t23.x);
                fma2(acc[nn][3], bb, t23.y);
            }
        }
        __syncthreads();
    }
    // epilogue: scale by a[n,k], write partials
#pragma unroll
    for (int nn = 0; nn < 4; nn++) {
        int n = ty * 4 + nn;
        float aw = a_s[n];
        float o[8];
#pragma unroll
        for (int m = 0; m < 4; m++) {
            float2 f = *(float2*)&acc[nn][m];
            o[m * 2] = f.x * aw;
            o[m * 2 + 1] = f.y * aw;
        }
        float* op = &d_partial[((size_t)(iz * 16 + k) * BB + n) * SS + jt * 128 + tx * 8];
        *(float4*)op = make_float4(o[0], o[1], o[2], o[3]);
        *(float4*)(op + 4) = make_float4(o[4], o[5], o[6], o[7]);
    }
}

// ---------------- per-step kernel 2: reduce partials + posterior softmax ----------------
// grid = 64 (one per n), 512 threads
__global__ void k_post(const float* __restrict__ lo_t, float* __restrict__ ab_t) {
    __shared__ float buf[16];
    int n = blockIdx.x, j = threadIdx.x;
    float s = 0.f;
#pragma unroll
    for (int c = 0; c < 64; c++) s += d_partial[((size_t)c * BB + n) * SS + j];
    float val = logf(s + EPSV) + lo_t[n * SS + j];
    float m = bmax512(val, buf);
    float e = expf(val - m);
    float sum = bsum512(e, buf);
    ab_t[n * SS + j] = e / sum;
}

// ---------------- batched plan (hoisted out of the sequential chain) ----------------
// grid (64 n, 8 hs), 256 threads. Block: logits[t][row] for 64 t x (4 h x 16 k) rows,
// then softmax over k per (t,h), weight by taupdf, sum over block's h -> pi partial.
#define PLAN_SMEM (65 * 64 * 8 + 64 * 66 * 4 + 64 * 68 * 4)
__global__ void k_plan(const float* __restrict__ alpha_b, const float* __restrict__ value) {
    extern __shared__ char sm[];
    unsigned long long(*Bs)[65] = (unsigned long long(*)[65])sm;                 // 33280 B
    float(*Vs)[66] = (float(*)[66])(sm + 65 * 64 * 8);                           // 16896 B
    float(*lg)[68] = (float(*)[68])(sm + 65 * 64 * 8 + 64 * 66 * 4);             // 17408 B

    int n = blockIdx.x, hs = blockIdx.y;
    int h0 = hs * 4;
    int tid = threadIdx.x;
    int tx = tid & 15;   // row group: row0 = tx*4
    int ty = tid >> 4;   // t group:   t0 = ty*4

    unsigned long long acc[4][2];
#pragma unroll
    for (int a = 0; a < 4; a++) { acc[a][0] = 0ull; acc[a][1] = 0ull; }

    for (int c = 0; c < 8; c++) {
        int i0 = c * 64;
        // Vs[ii][row] <- value[h0+hh][n][kk][i0+ii],  row = hh*16+kk
#pragma unroll
        for (int l = 0; l < 16; l++) {
            int idx = l * 256 + tid;
            int ii = idx & 63, row = idx >> 6;
            int hh = row >> 4, kk = row & 15;
            Vs[ii][row] = value[(((size_t)(h0 + hh) * BB + n) * AA + kk) * SS + i0 + ii];
        }
        // Bs[ii][t] <- packed alpha_b[t][n][i0+ii]
#pragma unroll
        for (int l = 0; l < 16; l++) {
            int idx = l * 256 + tid;
            int ii = idx & 63, t = idx >> 6;
            Bs[ii][t] = pack2(alpha_b[((size_t)t * BB + n) * SS + i0 + ii]);
        }
        __syncthreads();
#pragma unroll 8
        for (int ii = 0; ii < 64; ii++) {
            unsigned long long v01 = *(const unsigned long long*)&Vs[ii][tx * 4];
            unsigned long long v23 = *(const unsigned long long*)&Vs[ii][tx * 4 + 2];
#pragma unroll
            for (int tt = 0; tt < 4; tt++) {
                unsigned long long bb = Bs[ii][ty * 4 + tt];
                fma2(acc[tt][0], bb, v01);
                fma2(acc[tt][1], bb, v23);
            }
        }
        __syncthreads();
    }
    // stash logits into smem
#pragma unroll
    for (int tt = 0; tt < 4; tt++) {
        int t = ty * 4 + tt;
        float2 f0 = *(float2*)&acc[tt][0];
        float2 f1 = *(float2*)&acc[tt][1];
        lg[t][tx * 4] = f0.x;
        lg[t][tx * 4 + 1] = f0.y;
        lg[t][tx * 4 + 2] = f1.x;
        lg[t][tx * 4 + 3] = f1.y;
    }
    __syncthreads();

    // one thread per (t, hh): softmax over k, weight by taupdf, reduce over hh via shfl
    {
        int t = tid >> 2, hh = tid & 3;
        const float* row = &lg[t][hh * 16];
        float mm = -3.402823466e38f;
#pragma unroll
        for (int k = 0; k < AA; k++) mm = fmaxf(mm, row[k]);
        float ex[AA], se = 0.f;
#pragma unroll
        for (int k = 0; k < AA; k++) { ex[k] = expf(row[k] - mm); se += ex[k]; }
        float tw = d_taupdf[h0 + hh] / se;
        float pv[AA];
#pragma unroll
        for (int k = 0; k < AA; k++) pv[k] = ex[k] * tw;
        // sum across the 4 hh lanes (lanes are consecutive, groups of 4 aligned)
#pragma unroll
        for (int k = 0; k < AA; k++) {
            pv[k] += __shfl_xor_sync(0xffffffffu, pv[k], 1);
            pv[k] += __shfl_xor_sync(0xffffffffu, pv[k], 2);
        }
        float* op = &d_pi_part[(((size_t)hs * TT + t) * BB + n) * AA];
#pragma unroll
        for (int q = 0; q < 4; q++) op[hh * 4 + q] = pv[hh * 4 + q];
    }
}

// sum the 8 h-split partials -> alpha_pi.  grid 256 x 256
__global__ void k_pisum(float* __restrict__ api) {
    int idx = blockIdx.x * 256 + threadIdx.x;  // < T*B*A = 65536
    float s = 0.f;
#pragma unroll
    for (int hs = 0; hs < 8; hs++) s += d_pi_part[(size_t)hs * TT * BB * AA + idx];
    api[idx] = s;
}

// ---------------- launch ----------------
extern "C" void kernel_launch(void* const* d_in, const int* in_sizes, int n_in,
                              void* d_out, int out_size) {
    const float* logp_o = (const float*)d_in[0];  // [T,B,S]
    const float* logp_u = (const float*)d_in[1];  // [T,B,A]
    const float* value  = (const float*)d_in[2];  // [H,B,A,S]
    const float* b      = (const float*)d_in[3];  // [B,S]
    const float* u      = (const float*)d_in[4];  // [S,R]
    const float* v      = (const float*)d_in[5];  // [A,R]
    const float* tau    = (const float*)d_in[6];  // [1,1]

    float* out = (float*)d_out;
    float* alpha_b  = out;                          // [T,B,S]
    float* alpha_pi = out + (size_t)TT * BB * SS;   // [T,B,A]

    cudaFuncSetAttribute(k_gemm, cudaFuncAttributeMaxDynamicSharedMemorySize, GEMM_SMEM);
    cudaFuncSetAttribute(k_plan, cudaFuncAttributeMaxDynamicSharedMemorySize, PLAN_SMEM);

    k_gram<<<SS, SS>>>(u);
    k_p<<<AA, SS>>>(u, v);
    k_tau<<<1, HH>>>(tau);
    k_alpha_a<<<16, 256>>>(logp_u);
    k_trans<<<AA * SS, SS>>>();

    for (int t = 0; t < TT; t++) {
        const float* bel = (t == 0) ? b : (alpha_b + (size_t)(t - 1) * BB * SS);
        dim3 g1(4, 16, 4);
        k_gemm<<<g1, 256, GEMM_SMEM>>>(bel, t);
        k_post<<<BB, 512>>>(logp_o + (size_t)t * BB * SS, alpha_b + (size_t)t * BB * SS);
    }

    dim3 gp(BB, 8);
    k_plan<<<gp, 256, PLAN_SMEM>>>(alpha_b, value);
    k_pisum<<<256, 256>>>(alpha_pi);
}

// round 5
// speedup vs baseline: 1.6821x; 1.1771x over previous
#include <cuda_runtime.h>
#include <math.h>

#define TT 64
#define BB 64
#define SS 512
#define AA 16
#define RR 64
#define HH 32
#define EPSV 1e-6f

// ---------------- scratch (no allocations allowed) ----------------
__device__ float d_T[AA * SS * SS];          // transition [k][i][j]  (16.8 MB)
__device__ float d_G[SS * SS];               // gram u u^T            (1 MB)
__device__ float d_p[AA * SS];               // p[k,i] = <u_i, v_k/||v_k||>
__device__ float d_alpha_a[TT * BB * AA];    // softmax(logp_u)
__device__ float d_taupdf[HH];               // normalized poisson pmf
__device__ float d_partial[64 * BB * SS];    // GEMM (iz,k)-split partials (8 MB)
__device__ float d_pi_part[8 * TT * BB * AA];// plan h-split partials (2 MB)

// ---------------- helpers ----------------
__device__ __forceinline__ void fma2(unsigned long long& d, unsigned long long a,
                                     unsigned long long b) {
    asm("fma.rn.f32x2 %0, %1, %2, %0;" : "+l"(d) : "l"(a), "l"(b));
}
__device__ __forceinline__ unsigned long long pack2(float x) {
    unsigned long long r;
    unsigned int xi = __float_as_uint(x);
    asm("mov.b64 %0, {%1, %1};" : "=l"(r) : "r"(xi));
    return r;
}

__device__ __forceinline__ float bmax512(float v, float* buf) {
    int lane = threadIdx.x & 31, w = threadIdx.x >> 5;
#pragma unroll
    for (int o = 16; o; o >>= 1) v = fmaxf(v, __shfl_xor_sync(0xffffffffu, v, o));
    if (!lane) buf[w] = v;
    __syncthreads();
    if (w == 0) {
        float x = (lane < 16) ? buf[lane] : -3.402823466e38f;
#pragma unroll
        for (int o = 8; o; o >>= 1) x = fmaxf(x, __shfl_xor_sync(0xffffffffu, x, o));
        if (!lane) buf[0] = x;
    }
    __syncthreads();
    float r = buf[0];
    __syncthreads();
    return r;
}
__device__ __forceinline__ float bsum512(float v, float* buf) {
    int lane = threadIdx.x & 31, w = threadIdx.x >> 5;
#pragma unroll
    for (int o = 16; o; o >>= 1) v += __shfl_xor_sync(0xffffffffu, v, o);
    if (!lane) buf[w] = v;
    __syncthreads();
    if (w == 0) {
        float x = (lane < 16) ? buf[lane] : 0.0f;
#pragma unroll
        for (int o = 8; o; o >>= 1) x += __shfl_xor_sync(0xffffffffu, x, o);
        if (!lane) buf[0] = x;
    }
    __syncthreads();
    float r = buf[0];
    __syncthreads();
    return r;
}

// ---------------- precompute 1: gram + p (merged) ----------------
// grid 528, 512 threads. blocks 0..511: gram row i. blocks 512..527: p for action k.
__global__ void k_pre1(const float* __restrict__ u, const float* __restrict__ v) {
    if (blockIdx.x < 512) {
        __shared__ float ui[RR];
        int i = blockIdx.x;
        if (threadIdx.x < RR) ui[threadIdx.x] = u[i * RR + threadIdx.x];
        __syncthreads();
        int j = threadIdx.x;
        const float* uj = u + j * RR;
        float s = 0.f;
#pragma unroll
        for (int r = 0; r < RR; r++) s += ui[r] * uj[r];
        d_G[i * SS + j] = s;
    } else {
        __shared__ float vk[RR];
        __shared__ float invn;
        int k = blockIdx.x - 512, tid = threadIdx.x;
        if (tid < RR) vk[tid] = v[k * RR + tid];
        __syncthreads();
        if (tid == 0) {
            float s = 0.f;
            for (int r = 0; r < RR; r++) s += vk[r] * vk[r];
            invn = rsqrtf(s);
        }
        __syncthreads();
        const float* ui = u + tid * RR;
        float dot = 0.f;
#pragma unroll
        for (int r = 0; r < RR; r++) dot += ui[r] * vk[r];
        d_p[k * SS + tid] = dot * invn;
    }
}

// ---------------- precompute 2: alpha_a + tau (merged) ----------------
// grid 17, 256 threads. blocks 0..15: alpha_a. block 16: tau pmf (32 threads).
__global__ void k_pre2(const float* __restrict__ logp_u, const float* __restrict__ tau) {
    if (blockIdx.x < 16) {
        int row = blockIdx.x * 256 + threadIdx.x;  // < T*B = 4096
        const float* r = logp_u + row * AA;
        float m = -3.402823466e38f;
#pragma unroll
        for (int k = 0; k < AA; k++) m = fmaxf(m, r[k]);
        float e[AA], s = 0.f;
#pragma unroll
        for (int k = 0; k < AA; k++) { e[k] = expf(r[k] - m); s += e[k]; }
        float inv = 1.0f / s;
        float* o = d_alpha_a + row * AA;
#pragma unroll
        for (int k = 0; k < AA; k++) o[k] = e[k] * inv;
    } else if (threadIdx.x < HH) {
        int h = threadIdx.x;
        float rate = log1pf(expf(tau[0]));
        float lp = (float)(h + 1) * logf(rate) - rate - lgammaf((float)(h + 2));
        float p = expf(lp);
        float s = p;
#pragma unroll
        for (int o = 16; o; o >>= 1) s += __shfl_xor_sync(0xffffffffu, s, o);
        d_taupdf[h] = p / s;
    }
}

// transition[k,i,:] = softmax_j(G[i,j] - 2 p[k,i] p[k,j]).  grid=AA*SS, 512 threads
__global__ void k_trans() {
    __shared__ float buf[16];
    int ki = blockIdx.x;
    int k = ki >> 9, i = ki & 511;
    int j = threadIdx.x;
    float pki = d_p[k * SS + i];
    float w = d_G[i * SS + j] - 2.0f * pki * d_p[k * SS + j];
    float m = bmax512(w, buf);
    float e = __expf(w - m);
    float s = bsum512(e, buf);
    d_T[(size_t)ki * SS + j] = e / s;
}

// ---------------- per-step kernel 1: GEMM partials ----------------
// grid (4 jt, 16 k, 4 iz), 256 threads, 4 blocks/SM -> all 256 blocks in one wave.
// partial[iz*16+k][n][jt*128+j] = a[n,k] * sum_{i in 128-chunk} bel[n,i] T[k,i,j]
// smem: Ts[64][128] (32KB) + Bs[64][68] (17KB) + a_s (256B)
#define GEMM_SMEM (64 * 128 * 4 + 64 * 68 * 4 + 256)
__global__ __launch_bounds__(256, 4) void k_gemm(const float* __restrict__ bel, int t) {
    extern __shared__ char sm[];
    float(*Ts)[128] = (float(*)[128])sm;
    float(*Bs)[68] = (float(*)[68])(sm + 64 * 128 * 4);
    float* a_s = (float*)(sm + 64 * 128 * 4 + 64 * 68 * 4);

    int tid = threadIdx.x;
    int jt = blockIdx.x, k = blockIdx.y, iz = blockIdx.z;
    if (tid < 64) a_s[tid] = d_alpha_a[(size_t)t * BB * AA + tid * AA + k];

    int tx = tid & 15;   // j group: j0 = jt*128 + tx*8
    int ty = tid >> 4;   // n group: n0 = ty*4

    unsigned long long acc[4][4];
#pragma unroll
    for (int a = 0; a < 4; a++)
#pragma unroll
        for (int b = 0; b < 4; b++) acc[a][b] = 0ull;

#pragma unroll
    for (int c = 0; c < 2; c++) {
        int i0 = iz * 128 + c * 64;
        // Ts[ii][j] <- T[k][i0+ii][jt*128+j]  (8192 floats, float4, coalesced)
#pragma unroll
        for (int l = 0; l < 8; l++) {
            int idx = l * 256 + tid;            // 0..2047
            int j4 = idx & 31, ii = idx >> 5;
            float4 t4 = *(const float4*)&d_T[((size_t)(k * SS + i0 + ii)) * SS + jt * 128 + j4 * 4];
            *(float4*)&Ts[ii][j4 * 4] = t4;
        }
        // Bs[ii][n] <- bel[n][i0+ii]  (transpose: 4 strided LDG + STS.128 along n)
#pragma unroll
        for (int l = 0; l < 4; l++) {
            int idx = l * 256 + tid;            // 0..1023
            int ii = idx & 63, n4 = idx >> 6;   // n4: 0..15
            float4 bv;
            bv.x = bel[(n4 * 4 + 0) * SS + i0 + ii];
            bv.y = bel[(n4 * 4 + 1) * SS + i0 + ii];
            bv.z = bel[(n4 * 4 + 2) * SS + i0 + ii];
            bv.w = bel[(n4 * 4 + 3) * SS + i0 + ii];
            *(float4*)&Bs[ii][n4 * 4] = bv;
        }
        __syncthreads();
#pragma unroll 8
        for (int ii = 0; ii < 64; ii++) {
            ulonglong2 t01 = *(const ulonglong2*)&Ts[ii][tx * 8];
            ulonglong2 t23 = *(const ulonglong2*)&Ts[ii][tx * 8 + 4];
            float4 bv = *(const float4*)&Bs[ii][ty * 4];
            unsigned long long b0 = pack2(bv.x), b1 = pack2(bv.y),
                               b2 = pack2(bv.z), b3 = pack2(bv.w);
            fma2(acc[0][0], b0, t01.x); fma2(acc[0][1], b0, t01.y);
            fma2(acc[0][2], b0, t23.x); fma2(acc[0][3], b0, t23.y);
            fma2(acc[1][0], b1, t01.x); fma2(acc[1][1], b1, t01.y);
            fma2(acc[1][2], b1, t23.x); fma2(acc[1][3], b1, t23.y);
            fma2(acc[2][0], b2, t01.x); fma2(acc[2][1], b2, t01.y);
            fma2(acc[2][2], b2, t23.x); fma2(acc[2][3], b2, t23.y);
            fma2(acc[3][0], b3, t01.x); fma2(acc[3][1], b3, t01.y);
            fma2(acc[3][2], b3, t23.x); fma2(acc[3][3], b3, t23.y);
        }
        __syncthreads();
    }
    // epilogue: scale by a[n,k], write partials
#pragma unroll
    for (int nn = 0; nn < 4; nn++) {
        int n = ty * 4 + nn;
        float aw = a_s[n];
        float o[8];
#pragma unroll
        for (int m = 0; m < 4; m++) {
            float2 f = *(float2*)&acc[nn][m];
            o[m * 2] = f.x * aw;
            o[m * 2 + 1] = f.y * aw;
        }
        float* op = &d_partial[((size_t)(iz * 16 + k) * BB + n) * SS + jt * 128 + tx * 8];
        *(float4*)op = make_float4(o[0], o[1], o[2], o[3]);
        *(float4*)(op + 4) = make_float4(o[4], o[5], o[6], o[7]);
    }
}

// ---------------- per-step kernel 2: reduce partials + posterior softmax ----------------
// grid = 64 (one per n), 512 threads
__global__ void k_post(const float* __restrict__ lo_t, float* __restrict__ ab_t) {
    __shared__ float buf[16];
    int n = blockIdx.x, j = threadIdx.x;
    float s = 0.f;
#pragma unroll
    for (int c = 0; c < 64; c++) s += d_partial[((size_t)c * BB + n) * SS + j];
    float val = logf(s + EPSV) + lo_t[n * SS + j];
    float m = bmax512(val, buf);
    float e = expf(val - m);
    float sum = bsum512(e, buf);
    ab_t[n * SS + j] = e / sum;
}

// ---------------- batched plan (hoisted out of the sequential chain) ----------------
// grid (64 n, 8 hs), 256 threads, 4/SM -> 512 blocks in one wave.
// smem: Vs[64][68] + Bs[64][68] + lg[64][68]
#define PLAN_SMEM (3 * 64 * 68 * 4)
__global__ __launch_bounds__(256, 4) void k_plan(const float* __restrict__ alpha_b,
                                                 const float* __restrict__ value) {
    extern __shared__ char sm[];
    float(*Vs)[68] = (float(*)[68])sm;
    float(*Bs)[68] = (float(*)[68])(sm + 64 * 68 * 4);
    float(*lg)[68] = (float(*)[68])(sm + 2 * 64 * 68 * 4);

    int n = blockIdx.x, hs = blockIdx.y;
    int h0 = hs * 4;
    int tid = threadIdx.x;
    int tx = tid & 15;   // row group: row0 = tx*4 (row = hh*16+kk)
    int ty = tid >> 4;   // t group:   t0 = ty*4

    unsigned long long acc[4][2];
#pragma unroll
    for (int a = 0; a < 4; a++) { acc[a][0] = 0ull; acc[a][1] = 0ull; }

    for (int c = 0; c < 8; c++) {
        int i0 = c * 64;
        // Vs[ii][row] <- value[h0+hh][n][kk][i0+ii], 4 rows per float4 store
#pragma unroll
        for (int l = 0; l < 4; l++) {
            int idx = l * 256 + tid;            // 0..1023
            int ii = idx & 63, r4 = idx >> 6;   // r4: 0..15
            float4 vv;
#pragma unroll
            for (int q = 0; q < 4; q++) {
                int row = r4 * 4 + q;
                int hh = row >> 4, kk = row & 15;
                ((float*)&vv)[q] = value[(((size_t)(h0 + hh) * BB + n) * AA + kk) * SS + i0 + ii];
            }
            *(float4*)&Vs[ii][r4 * 4] = vv;
        }
        // Bs[ii][t] <- alpha_b[t][n][i0+ii]
#pragma unroll
        for (int l = 0; l < 4; l++) {
            int idx = l * 256 + tid;
            int ii = idx & 63, t4 = idx >> 6;
            float4 bv;
            bv.x = alpha_b[((size_t)(t4 * 4 + 0) * BB + n) * SS + i0 + ii];
            bv.y = alpha_b[((size_t)(t4 * 4 + 1) * BB + n) * SS + i0 + ii];
            bv.z = alpha_b[((size_t)(t4 * 4 + 2) * BB + n) * SS + i0 + ii];
            bv.w = alpha_b[((size_t)(t4 * 4 + 3) * BB + n) * SS + i0 + ii];
            *(float4*)&Bs[ii][t4 * 4] = bv;
        }
        __syncthreads();
#pragma unroll 8
        for (int ii = 0; ii < 64; ii++) {
            ulonglong2 vv = *(const ulonglong2*)&Vs[ii][tx * 4];
            float4 bv = *(const float4*)&Bs[ii][ty * 4];
            unsigned long long b0 = pack2(bv.x), b1 = pack2(bv.y),
                               b2 = pack2(bv.z), b3 = pack2(bv.w);
            fma2(acc[0][0], b0, vv.x); fma2(acc[0][1], b0, vv.y);
            fma2(acc[1][0], b1, vv.x); fma2(acc[1][1], b1, vv.y);
            fma2(acc[2][0], b2, vv.x); fma2(acc[2][1], b2, vv.y);
            fma2(acc[3][0], b3, vv.x); fma2(acc[3][1], b3, vv.y);
        }
        __syncthreads();
    }
    // stash logits into smem: lg[t][row]
#pragma unroll
    for (int tt = 0; tt < 4; tt++) {
        int t = ty * 4 + tt;
        float2 f0 = *(float2*)&acc[tt][0];
        float2 f1 = *(float2*)&acc[tt][1];
        lg[t][tx * 4] = f0.x;
        lg[t][tx * 4 + 1] = f0.y;
        lg[t][tx * 4 + 2] = f1.x;
        lg[t][tx * 4 + 3] = f1.y;
    }
    __syncthreads();

    // one thread per (t, hh): softmax over k, weight by taupdf, reduce over hh via shfl
    {
        int t = tid >> 2, hh = tid & 3;
        const float* row = &lg[t][hh * 16];
        float mm = -3.402823466e38f;
#pragma unroll
        for (int k = 0; k < AA; k++) mm = fmaxf(mm, row[k]);
        float ex[AA], se = 0.f;
#pragma unroll
        for (int k = 0; k < AA; k++) { ex[k] = expf(row[k] - mm); se += ex[k]; }
        float tw = d_taupdf[h0 + hh] / se;
        float pv[AA];
#pragma unroll
        for (int k = 0; k < AA; k++) pv[k] = ex[k] * tw;
#pragma unroll
        for (int k = 0; k < AA; k++) {
            pv[k] += __shfl_xor_sync(0xffffffffu, pv[k], 1);
            pv[k] += __shfl_xor_sync(0xffffffffu, pv[k], 2);
        }
        float* op = &d_pi_part[(((size_t)hs * TT + t) * BB + n) * AA];
#pragma unroll
        for (int q = 0; q < 4; q++) op[hh * 4 + q] = pv[hh * 4 + q];
    }
}

// sum the 8 h-split partials -> alpha_pi.  grid 256 x 256
__global__ void k_pisum(float* __restrict__ api) {
    int idx = blockIdx.x * 256 + threadIdx.x;  // < T*B*A = 65536
    float s = 0.f;
#pragma unroll
    for (int hs = 0; hs < 8; hs++) s += d_pi_part[(size_t)hs * TT * BB * AA + idx];
    api[idx] = s;
}

// ---------------- launch ----------------
extern "C" void kernel_launch(void* const* d_in, const int* in_sizes, int n_in,
                              void* d_out, int out_size) {
    const float* logp_o = (const float*)d_in[0];  // [T,B,S]
    const float* logp_u = (const float*)d_in[1];  // [T,B,A]
    const float* value  = (const float*)d_in[2];  // [H,B,A,S]
    const float* b      = (const float*)d_in[3];  // [B,S]
    const float* u      = (const float*)d_in[4];  // [S,R]
    const float* v      = (const float*)d_in[5];  // [A,R]
    const float* tau    = (const float*)d_in[6];  // [1,1]

    float* out = (float*)d_out;
    float* alpha_b  = out;                          // [T,B,S]
    float* alpha_pi = out + (size_t)TT * BB * SS;   // [T,B,A]

    cudaFuncSetAttribute(k_gemm, cudaFuncAttributeMaxDynamicSharedMemorySize, GEMM_SMEM);
    cudaFuncSetAttribute(k_plan, cudaFuncAttributeMaxDynamicSharedMemorySize, PLAN_SMEM);

    k_pre1<<<528, 512>>>(u, v);
    k_pre2<<<17, 256>>>(logp_u, tau);
    k_trans<<<AA * SS, 512>>>();

    for (int t = 0; t < TT; t++) {
        const float* bel = (t == 0) ? b : (alpha_b + (size_t)(t - 1) * BB * SS);
        dim3 g1(4, 16, 4);
        k_gemm<<<g1, 256, GEMM_SMEM>>>(bel, t);
        k_post<<<BB, 512>>>(logp_o + (size_t)t * BB * SS, alpha_b + (size_t)t * BB * SS);
    }

    dim3 gp(BB, 8);
    k_plan<<<gp, 256, PLAN_SMEM>>>(alpha_b, value);
    k_pisum<<<256, 256>>>(alpha_pi);
}

// round 7
// speedup vs baseline: 2.5441x; 1.5125x over previous
#include <cuda_runtime.h>
#include <math.h>

#define TT 64
#define BB 64
#define SS 512
#define AA 16
#define RR 64
#define HH 32
#define EPSV 1e-6f

// ---------------- scratch (no allocations allowed) ----------------
__device__ float d_T[AA * SS * SS];          // transition [k][i][j]  (16.8 MB)
__device__ float d_G[SS * SS];               // gram u u^T            (1 MB)
__device__ float d_p[AA * SS];               // p[k,i] = <u_i, v_k/||v_k||>
__device__ float d_alpha_a[TT * BB * AA];    // softmax(logp_u)
__device__ float d_taupdf[HH];               // normalized poisson pmf
__device__ float d_partial[64 * BB * SS];    // GEMM (kp,iz)-split partials (8 MB)
__device__ float d_pi_part[8 * TT * BB * AA];// plan h-split partials (2 MB)

// ---------------- helpers ----------------
__device__ __forceinline__ void fma2(unsigned long long& d, unsigned long long a,
                                     unsigned long long b) {
    asm("fma.rn.f32x2 %0, %1, %2, %0;" : "+l"(d) : "l"(a), "l"(b));
}
__device__ __forceinline__ unsigned long long pack2(float x) {
    unsigned long long r;
    unsigned int xi = __float_as_uint(x);
    asm("mov.b64 %0, {%1, %1};" : "=l"(r) : "r"(xi));
    return r;
}

__device__ __forceinline__ float bmax512(float v, float* buf) {
    int lane = threadIdx.x & 31, w = threadIdx.x >> 5;
#pragma unroll
    for (int o = 16; o; o >>= 1) v = fmaxf(v, __shfl_xor_sync(0xffffffffu, v, o));
    if (!lane) buf[w] = v;
    __syncthreads();
    if (w == 0) {
        float x = (lane < 16) ? buf[lane] : -3.402823466e38f;
#pragma unroll
        for (int o = 8; o; o >>= 1) x = fmaxf(x, __shfl_xor_sync(0xffffffffu, x, o));
        if (!lane) buf[0] = x;
    }
    __syncthreads();
    float r = buf[0];
    __syncthreads();
    return r;
}
__device__ __forceinline__ float bsum512(float v, float* buf) {
    int lane = threadIdx.x & 31, w = threadIdx.x >> 5;
#pragma unroll
    for (int o = 16; o; o >>= 1) v += __shfl_xor_sync(0xffffffffu, v, o);
    if (!lane) buf[w] = v;
    __syncthreads();
    if (w == 0) {
        float x = (lane < 16) ? buf[lane] : 0.0f;
#pragma unroll
        for (int o = 8; o; o >>= 1) x += __shfl_xor_sync(0xffffffffu, x, o);
        if (!lane) buf[0] = x;
    }
    __syncthreads();
    float r = buf[0];
    __syncthreads();
    return r;
}

// ---------------- precompute 1: gram + p (merged) ----------------
__global__ void k_pre1(const float* __restrict__ u, const float* __restrict__ v) {
    if (blockIdx.x < 512) {
        __shared__ float ui[RR];
        int i = blockIdx.x;
        if (threadIdx.x < RR) ui[threadIdx.x] = u[i * RR + threadIdx.x];
        __syncthreads();
        int j = threadIdx.x;
        const float* uj = u + j * RR;
        float s = 0.f;
#pragma unroll
        for (int r = 0; r < RR; r++) s += ui[r] * uj[r];
        d_G[i * SS + j] = s;
    } else {
        __shared__ float vk[RR];
        __shared__ float invn;
        int k = blockIdx.x - 512, tid = threadIdx.x;
        if (tid < RR) vk[tid] = v[k * RR + tid];
        __syncthreads();
        if (tid == 0) {
            float s = 0.f;
            for (int r = 0; r < RR; r++) s += vk[r] * vk[r];
            invn = rsqrtf(s);
        }
        __syncthreads();
        const float* ui = u + tid * RR;
        float dot = 0.f;
#pragma unroll
        for (int r = 0; r < RR; r++) dot += ui[r] * vk[r];
        d_p[k * SS + tid] = dot * invn;
    }
}

// ---------------- precompute 2: alpha_a + tau (merged) ----------------
__global__ void k_pre2(const float* __restrict__ logp_u, const float* __restrict__ tau) {
    if (blockIdx.x < 16) {
        int row = blockIdx.x * 256 + threadIdx.x;  // < T*B = 4096
        const float* r = logp_u + row * AA;
        float m = -3.402823466e38f;
#pragma unroll
        for (int k = 0; k < AA; k++) m = fmaxf(m, r[k]);
        float e[AA], s = 0.f;
#pragma unroll
        for (int k = 0; k < AA; k++) { e[k] = expf(r[k] - m); s += e[k]; }
        float inv = 1.0f / s;
        float* o = d_alpha_a + row * AA;
#pragma unroll
        for (int k = 0; k < AA; k++) o[k] = e[k] * inv;
    } else if (threadIdx.x < HH) {
        int h = threadIdx.x;
        float rate = log1pf(expf(tau[0]));
        float lp = (float)(h + 1) * logf(rate) - rate - lgammaf((float)(h + 2));
        float p = expf(lp);
        float s = p;
#pragma unroll
        for (int o = 16; o; o >>= 1) s += __shfl_xor_sync(0xffffffffu, s, o);
        d_taupdf[h] = p / s;
    }
}

// transition[k,i,:] = softmax_j(G[i,j] - 2 p[k,i] p[k,j]).  grid=AA*SS, 512 threads
__global__ void k_trans() {
    __shared__ float buf[16];
    int ki = blockIdx.x;
    int k = ki >> 9, i = ki & 511;
    int j = threadIdx.x;
    float pki = d_p[k * SS + i];
    float w = d_G[i * SS + j] - 2.0f * pki * d_p[k * SS + j];
    float m = bmax512(w, buf);
    float e = __expf(w - m);
    float s = bsum512(e, buf);
    d_T[(size_t)ki * SS + j] = e / s;
}

// ---------------- per-step kernel 1: GEMM partials (n-broadcast warp tiling) ---------
// grid (4 jt, 8 kp, 8 iz) = 256 blocks, 256 threads, 2 blocks/SM -> single wave.
// Warp w: n in [8w, 8w+8) (broadcast across lanes), lane: j = jt*128 + lane*4.
// Each block handles a k-PAIR (k0=2kp, k0+1) sharing the Bs tile; epilogue combines:
//   partial[kp*8+iz][n][j] = sum_{kk} a[n,k0+kk] * sum_{ii in 64-chunk} bel[n,ii] T[k][ii][j]
// Accumulators are f32x2 pairs over n (bel pairs come straight from broadcast LDS.128).
#define GEMM_SMEM (64 * 128 * 4 + 64 * 68 * 4 + 2 * 64 * 4)
__global__ __launch_bounds__(256, 2) void k_gemm(const float* __restrict__ bel, int t) {
    extern __shared__ char sm[];
    float(*Ts)[128] = (float(*)[128])sm;                          // 32768 B
    float(*Bs)[68] = (float(*)[68])(sm + 64 * 128 * 4);           // 17408 B
    float(*a_s)[64] = (float(*)[64])(sm + 64 * 128 * 4 + 64 * 68 * 4);  // 512 B

    int tid = threadIdx.x;
    int w = tid >> 5, lane = tid & 31;
    int jt = blockIdx.x, kp = blockIdx.y, iz = blockIdx.z;
    int k0 = kp * 2;
    int i0 = iz * 64;

    if (tid < 64) {
        a_s[0][tid] = d_alpha_a[(size_t)t * BB * AA + tid * AA + k0];
        a_s[1][tid] = d_alpha_a[(size_t)t * BB * AA + tid * AA + k0 + 1];
    }

    // Bs[ii][n] <- bel[n][i0+ii]  (transpose; shared by both k phases)
#pragma unroll
    for (int l = 0; l < 4; l++) {
        int idx = l * 256 + tid;            // 0..1023
        int ii = idx & 63, n4 = idx >> 6;   // n4: 0..15
        float4 bv;
        bv.x = bel[(n4 * 4 + 0) * SS + i0 + ii];
        bv.y = bel[(n4 * 4 + 1) * SS + i0 + ii];
        bv.z = bel[(n4 * 4 + 2) * SS + i0 + ii];
        bv.w = bel[(n4 * 4 + 3) * SS + i0 + ii];
        *(float4*)&Bs[ii][n4 * 4] = bv;
    }

    // acc[kk][p][j]: f32x2 over n-pair p (n = 8w+2p, 8w+2p+1), j = lane*4 + j
    unsigned long long acc[2][4][4];
#pragma unroll
    for (int kk = 0; kk < 2; kk++)
#pragma unroll
        for (int p = 0; p < 4; p++)
#pragma unroll
            for (int j = 0; j < 4; j++) acc[kk][p][j] = 0ull;

#pragma unroll
    for (int kk = 0; kk < 2; kk++) {
        __syncthreads();  // Bs/a_s ready (kk=0); Ts consumed by previous phase (kk=1)
        // Ts[ii][j] <- T[k0+kk][i0+ii][jt*128 + j]
#pragma unroll
        for (int l = 0; l < 8; l++) {
            int idx = l * 256 + tid;        // 0..2047
            int ii = idx >> 5, j4 = idx & 31;
            *(float4*)&Ts[ii][j4 * 4] =
                *(const float4*)&d_T[((size_t)((k0 + kk) * SS + i0 + ii)) * SS + jt * 128 + j4 * 4];
        }
        __syncthreads();
#pragma unroll 8
        for (int ii = 0; ii < 64; ii++) {
            ulonglong2 b01 = *(const ulonglong2*)&Bs[ii][w * 8];       // bel n..n+3 (2 pairs)
            ulonglong2 b23 = *(const ulonglong2*)&Bs[ii][w * 8 + 4];   // bel n+4..n+7
            float4 tv = *(const float4*)&Ts[ii][lane * 4];
            unsigned long long t0 = pack2(tv.x), t1 = pack2(tv.y),
                               t2 = pack2(tv.z), t3 = pack2(tv.w);
            fma2(acc[kk][0][0], b01.x, t0); fma2(acc[kk][0][1], b01.x, t1);
            fma2(acc[kk][0][2], b01.x, t2); fma2(acc[kk][0][3], b01.x, t3);
            fma2(acc[kk][1][0], b01.y, t0); fma2(acc[kk][1][1], b01.y, t1);
            fma2(acc[kk][1][2], b01.y, t2); fma2(acc[kk][1][3], b01.y, t3);
            fma2(acc[kk][2][0], b23.x, t0); fma2(acc[kk][2][1], b23.x, t1);
            fma2(acc[kk][2][2], b23.x, t2); fma2(acc[kk][2][3], b23.x, t3);
            fma2(acc[kk][3][0], b23.y, t0); fma2(acc[kk][3][1], b23.y, t1);
            fma2(acc[kk][3][2], b23.y, t2); fma2(acc[kk][3][3], b23.y, t3);
        }
    }

    // epilogue: combine k-pair with a-weights, write one partial slice
    int c = kp * 8 + iz;
#pragma unroll
    for (int p = 0; p < 4; p++) {
#pragma unroll
        for (int par = 0; par < 2; par++) {
            int n = w * 8 + p * 2 + par;
            float a0 = a_s[0][n], a1 = a_s[1][n];
            float4 o;
#pragma unroll
            for (int j = 0; j < 4; j++) {
                float2 f0 = *(float2*)&acc[0][p][j];
                float2 f1 = *(float2*)&acc[1][p][j];
                float v0 = par ? f0.y : f0.x;
                float v1 = par ? f1.y : f1.x;
                ((float*)&o)[j] = v0 * a0 + v1 * a1;
            }
            *(float4*)&d_partial[((size_t)c * BB + n) * SS + jt * 128 + lane * 4] = o;
        }
    }
}

// ---------------- per-step kernel 2: reduce partials + posterior softmax ----------------
// grid = 64 (one per n), 512 threads
__global__ void k_post(const float* __restrict__ lo_t, float* __restrict__ ab_t) {
    __shared__ float buf[16];
    int n = blockIdx.x, j = threadIdx.x;
    float s = 0.f;
#pragma unroll
    for (int c = 0; c < 64; c++) s += d_partial[((size_t)c * BB + n) * SS + j];
    float val = __logf(s + EPSV) + lo_t[n * SS + j];
    float m = bmax512(val, buf);
    float e = __expf(val - m);
    float sum = bsum512(e, buf);
    ab_t[n * SS + j] = e / sum;
}

// ---------------- batched plan (hoisted out of the sequential chain) ----------------
#define PLAN_SMEM (3 * 64 * 68 * 4)
__global__ __launch_bounds__(256, 4) void k_plan(const float* __restrict__ alpha_b,
                                                 const float* __restrict__ value) {
    extern __shared__ char sm[];
    float(*Vs)[68] = (float(*)[68])sm;
    float(*Bs)[68] = (float(*)[68])(sm + 64 * 68 * 4);
    float(*lg)[68] = (float(*)[68])(sm + 2 * 64 * 68 * 4);

    int n = blockIdx.x, hs = blockIdx.y;
    int h0 = hs * 4;
    int tid = threadIdx.x;
    int tx = tid & 15;   // row group: row0 = tx*4 (row = hh*16+kk)
    int ty = tid >> 4;   // t group:   t0 = ty*4

    unsigned long long acc[4][2];
#pragma unroll
    for (int a = 0; a < 4; a++) { acc[a][0] = 0ull; acc[a][1] = 0ull; }

    for (int c = 0; c < 8; c++) {
        int i0 = c * 64;
#pragma unroll
        for (int l = 0; l < 4; l++) {
            int idx = l * 256 + tid;
            int ii = idx & 63, r4 = idx >> 6;
            float4 vv;
#pragma unroll
            for (int q = 0; q < 4; q++) {
                int row = r4 * 4 + q;
                int hh = row >> 4, kk = row & 15;
                ((float*)&vv)[q] = value[(((size_t)(h0 + hh) * BB + n) * AA + kk) * SS + i0 + ii];
            }
            *(float4*)&Vs[ii][r4 * 4] = vv;
        }
#pragma unroll
        for (int l = 0; l < 4; l++) {
            int idx = l * 256 + tid;
            int ii = idx & 63, t4 = idx >> 6;
            float4 bv;
            bv.x = alpha_b[((size_t)(t4 * 4 + 0) * BB + n) * SS + i0 + ii];
            bv.y = alpha_b[((size_t)(t4 * 4 + 1) * BB + n) * SS + i0 + ii];
            bv.z = alpha_b[((size_t)(t4 * 4 + 2) * BB + n) * SS + i0 + ii];
            bv.w = alpha_b[((size_t)(t4 * 4 + 3) * BB + n) * SS + i0 + ii];
            *(float4*)&Bs[ii][t4 * 4] = bv;
        }
        __syncthreads();
#pragma unroll 8
        for (int ii = 0; ii < 64; ii++) {
            ulonglong2 vv = *(const ulonglong2*)&Vs[ii][tx * 4];
            float4 bv = *(const float4*)&Bs[ii][ty * 4];
            unsigned long long b0 = pack2(bv.x), b1 = pack2(bv.y),
                               b2 = pack2(bv.z), b3 = pack2(bv.w);
            fma2(acc[0][0], b0, vv.x); fma2(acc[0][1], b0, vv.y);
            fma2(acc[1][0], b1, vv.x); fma2(acc[1][1], b1, vv.y);
            fma2(acc[2][0], b2, vv.x); fma2(acc[2][1], b2, vv.y);
            fma2(acc[3][0], b3, vv.x); fma2(acc[3][1], b3, vv.y);
        }
        __syncthreads();
    }
#pragma unroll
    for (int tt = 0; tt < 4; tt++) {
        int t = ty * 4 + tt;
        float2 f0 = *(float2*)&acc[tt][0];
        float2 f1 = *(float2*)&acc[tt][1];
        lg[t][tx * 4] = f0.x;
        lg[t][tx * 4 + 1] = f0.y;
        lg[t][tx * 4 + 2] = f1.x;
        lg[t][tx * 4 + 3] = f1.y;
    }
    __syncthreads();

    {
        int t = tid >> 2, hh = tid & 3;
        const float* row = &lg[t][hh * 16];
        float mm = -3.402823466e38f;
#pragma unroll
        for (int k = 0; k < AA; k++) mm = fmaxf(mm, row[k]);
        float ex[AA], se = 0.f;
#pragma unroll
        for (int k = 0; k < AA; k++) { ex[k] = __expf(row[k] - mm); se += ex[k]; }
        float tw = d_taupdf[h0 + hh] / se;
        float pv[AA];
#pragma unroll
        for (int k = 0; k < AA; k++) pv[k] = ex[k] * tw;
#pragma unroll
        for (int k = 0; k < AA; k++) {
            pv[k] += __shfl_xor_sync(0xffffffffu, pv[k], 1);
            pv[k] += __shfl_xor_sync(0xffffffffu, pv[k], 2);
        }
        float* op = &d_pi_part[(((size_t)hs * TT + t) * BB + n) * AA];
#pragma unroll
        for (int q = 0; q < 4; q++) op[hh * 4 + q] = pv[hh * 4 + q];
    }
}

// sum the 8 h-split partials -> alpha_pi.  grid 256 x 256
__global__ void k_pisum(float* __restrict__ api) {
    int idx = blockIdx.x * 256 + threadIdx.x;  // < T*B*A = 65536
    float s = 0.f;
#pragma unroll
    for (int hs = 0; hs < 8; hs++) s += d_pi_part[(size_t)hs * TT * BB * AA + idx];
    api[idx] = s;
}

// ---------------- launch ----------------
extern "C" void kernel_launch(void* const* d_in, const int* in_sizes, int n_in,
                              void* d_out, int out_size) {
    const float* logp_o = (const float*)d_in[0];  // [T,B,S]
    const float* logp_u = (const float*)d_in[1];  // [T,B,A]
    const float* value  = (const float*)d_in[2];  // [H,B,A,S]
    const float* b      = (const float*)d_in[3];  // [B,S]
    const float* u      = (const float*)d_in[4];  // [S,R]
    const float* v      = (const float*)d_in[5];  // [A,R]
    const float* tau    = (const float*)d_in[6];  // [1,1]

    float* out = (float*)d_out;
    float* alpha_b  = out;                          // [T,B,S]
    float* alpha_pi = out + (size_t)TT * BB * SS;   // [T,B,A]

    cudaFuncSetAttribute(k_gemm, cudaFuncAttributeMaxDynamicSharedMemorySize, GEMM_SMEM);
    cudaFuncSetAttribute(k_plan, cudaFuncAttributeMaxDynamicSharedMemorySize, PLAN_SMEM);

    k_pre1<<<528, 512>>>(u, v);
    k_pre2<<<17, 256>>>(logp_u, tau);
    k_trans<<<AA * SS, 512>>>();

    for (int t = 0; t < TT; t++) {
        const float* bel = (t == 0) ? b : (alpha_b + (size_t)(t - 1) * BB * SS);
        dim3 g1(4, 8, 8);
        k_gemm<<<g1, 256, GEMM_SMEM>>>(bel, t);
        k_post<<<BB, 512>>>(logp_o + (size_t)t * BB * SS, alpha_b + (size_t)t * BB * SS);
    }

    dim3 gp(BB, 8);
    k_plan<<<gp, 256, PLAN_SMEM>>>(alpha_b, value);
    k_pisum<<<256, 256>>>(alpha_pi);
}

// round 9
// speedup vs baseline: 2.5473x; 1.0012x over previous
#include <cuda_runtime.h>
#include <math.h>

#define TT 64
#define BB 64
#define SS 512
#define AA 16
#define RR 64
#define HH 32
#define EPSV 1e-6f

// ---------------- scratch (no allocations allowed) ----------------
__device__ float d_T[AA * SS * SS];          // transition [k][i][j]  (16.8 MB)
__device__ float d_G[SS * SS];               // gram u u^T            (1 MB)
__device__ float d_p[AA * SS];               // p[k,i] = <u_i, v_k/||v_k||>
__device__ float d_alpha_a[TT * BB * AA];    // softmax(logp_u)
__device__ float d_taupdf[HH];               // normalized poisson pmf
__device__ float d_partial[64 * BB * SS];    // GEMM (kp,iz)-split partials (8 MB)
__device__ float d_pi_part[8 * TT * BB * AA];// plan h-split partials (2 MB)

// ---------------- helpers ----------------
__device__ __forceinline__ void fma2(unsigned long long& d, unsigned long long a,
                                     unsigned long long b) {
    asm("fma.rn.f32x2 %0, %1, %2, %0;" : "+l"(d) : "l"(a), "l"(b));
}
__device__ __forceinline__ unsigned long long pack2(float x) {
    unsigned long long r;
    unsigned int xi = __float_as_uint(x);
    asm("mov.b64 %0, {%1, %1};" : "=l"(r) : "r"(xi));
    return r;
}

__device__ __forceinline__ float bmax512(float v, float* buf) {
    int lane = threadIdx.x & 31, w = threadIdx.x >> 5;
#pragma unroll
    for (int o = 16; o; o >>= 1) v = fmaxf(v, __shfl_xor_sync(0xffffffffu, v, o));
    if (!lane) buf[w] = v;
    __syncthreads();
    if (w == 0) {
        float x = (lane < 16) ? buf[lane] : -3.402823466e38f;
#pragma unroll
        for (int o = 8; o; o >>= 1) x = fmaxf(x, __shfl_xor_sync(0xffffffffu, x, o));
        if (!lane) buf[0] = x;
    }
    __syncthreads();
    float r = buf[0];
    __syncthreads();
    return r;
}
__device__ __forceinline__ float bsum512(float v, float* buf) {
    int lane = threadIdx.x & 31, w = threadIdx.x >> 5;
#pragma unroll
    for (int o = 16; o; o >>= 1) v += __shfl_xor_sync(0xffffffffu, v, o);
    if (!lane) buf[w] = v;
    __syncthreads();
    if (w == 0) {
        float x = (lane < 16) ? buf[lane] : 0.0f;
#pragma unroll
        for (int o = 8; o; o >>= 1) x += __shfl_xor_sync(0xffffffffu, x, o);
        if (!lane) buf[0] = x;
    }
    __syncthreads();
    float r = buf[0];
    __syncthreads();
    return r;
}

// ---------------- precompute 1: gram + p (merged) ----------------
__global__ void k_pre1(const float* __restrict__ u, const float* __restrict__ v) {
    if (blockIdx.x < 512) {
        __shared__ float ui[RR];
        int i = blockIdx.x;
        if (threadIdx.x < RR) ui[threadIdx.x] = u[i * RR + threadIdx.x];
        __syncthreads();
        int j = threadIdx.x;
        const float* uj = u + j * RR;
        float s = 0.f;
#pragma unroll
        for (int r = 0; r < RR; r++) s += ui[r] * uj[r];
        d_G[i * SS + j] = s;
    } else {
        __shared__ float vk[RR];
        __shared__ float invn;
        int k = blockIdx.x - 512, tid = threadIdx.x;
        if (tid < RR) vk[tid] = v[k * RR + tid];
        __syncthreads();
        if (tid == 0) {
            float s = 0.f;
            for (int r = 0; r < RR; r++) s += vk[r] * vk[r];
            invn = rsqrtf(s);
        }
        __syncthreads();
        const float* ui = u + tid * RR;
        float dot = 0.f;
#pragma unroll
        for (int r = 0; r < RR; r++) dot += ui[r] * vk[r];
        d_p[k * SS + tid] = dot * invn;
    }
}

// ---------------- precompute 2: alpha_a + tau (merged) ----------------
__global__ void k_pre2(const float* __restrict__ logp_u, const float* __restrict__ tau) {
    if (blockIdx.x < 16) {
        int row = blockIdx.x * 256 + threadIdx.x;  // < T*B = 4096
        const float* r = logp_u + row * AA;
        float m = -3.402823466e38f;
#pragma unroll
        for (int k = 0; k < AA; k++) m = fmaxf(m, r[k]);
        float e[AA], s = 0.f;
#pragma unroll
        for (int k = 0; k < AA; k++) { e[k] = expf(r[k] - m); s += e[k]; }
        float inv = 1.0f / s;
        float* o = d_alpha_a + row * AA;
#pragma unroll
        for (int k = 0; k < AA; k++) o[k] = e[k] * inv;
    } else if (threadIdx.x < HH) {
        int h = threadIdx.x;
        float rate = log1pf(expf(tau[0]));
        float lp = (float)(h + 1) * logf(rate) - rate - lgammaf((float)(h + 2));
        float p = expf(lp);
        float s = p;
#pragma unroll
        for (int o = 16; o; o >>= 1) s += __shfl_xor_sync(0xffffffffu, s, o);
        d_taupdf[h] = p / s;
    }
}

// transition[k,i,:] = softmax_j(G[i,j] - 2 p[k,i] p[k,j]).  grid=AA*SS, 512 threads
__global__ void k_trans() {
    __shared__ float buf[16];
    int ki = blockIdx.x;
    int k = ki >> 9, i = ki & 511;
    int j = threadIdx.x;
    float pki = d_p[k * SS + i];
    float w = d_G[i * SS + j] - 2.0f * pki * d_p[k * SS + j];
    float m = bmax512(w, buf);
    float e = __expf(w - m);
    float s = bsum512(e, buf);
    d_T[(size_t)ki * SS + j] = e / s;
}

// ---------------- per-step kernel 1: GEMM partials (n-broadcast warp tiling) ---------
// grid (4 jt, 8 kp, 8 iz) = 256 blocks, 256 threads, 2 blocks/SM -> single wave.
// Warp w: n in [8w, 8w+8) (broadcast across lanes), lane: j = jt*128 + lane*4.
// Each block handles a k-PAIR (k0=2kp, k0+1) sharing the Bs tile; epilogue combines:
//   partial[kp*8+iz][n][j] = sum_{kk} a[n,k0+kk] * sum_{ii in 64-chunk} bel[n,ii] T[k][ii][j]
// Accumulators are f32x2 pairs over n (bel pairs come straight from broadcast LDS.128).
#define GEMM_SMEM (64 * 128 * 4 + 64 * 68 * 4 + 2 * 64 * 4)
__global__ __launch_bounds__(256, 2) void k_gemm(const float* __restrict__ bel, int t) {
    extern __shared__ char sm[];
    float(*Ts)[128] = (float(*)[128])sm;                          // 32768 B
    float(*Bs)[68] = (float(*)[68])(sm + 64 * 128 * 4);           // 17408 B
    float(*a_s)[64] = (float(*)[64])(sm + 64 * 128 * 4 + 64 * 68 * 4);  // 512 B

    int tid = threadIdx.x;
    int w = tid >> 5, lane = tid & 31;
    int jt = blockIdx.x, kp = blockIdx.y, iz = blockIdx.z;
    int k0 = kp * 2;
    int i0 = iz * 64;

    if (tid < 64) {
        a_s[0][tid] = d_alpha_a[(size_t)t * BB * AA + tid * AA + k0];
        a_s[1][tid] = d_alpha_a[(size_t)t * BB * AA + tid * AA + k0 + 1];
    }

    // Bs[ii][n] <- bel[n][i0+ii]  (transpose; shared by both k phases)
#pragma unroll
    for (int l = 0; l < 4; l++) {
        int idx = l * 256 + tid;            // 0..1023
        int ii = idx & 63, n4 = idx >> 6;   // n4: 0..15
        float4 bv;
        bv.x = bel[(n4 * 4 + 0) * SS + i0 + ii];
        bv.y = bel[(n4 * 4 + 1) * SS + i0 + ii];
        bv.z = bel[(n4 * 4 + 2) * SS + i0 + ii];
        bv.w = bel[(n4 * 4 + 3) * SS + i0 + ii];
        *(float4*)&Bs[ii][n4 * 4] = bv;
    }

    // acc[kk][p][j]: f32x2 over n-pair p (n = 8w+2p, 8w+2p+1), j = lane*4 + j
    unsigned long long acc[2][4][4];
#pragma unroll
    for (int kk = 0; kk < 2; kk++)
#pragma unroll
        for (int p = 0; p < 4; p++)
#pragma unroll
            for (int j = 0; j < 4; j++) acc[kk][p][j] = 0ull;

#pragma unroll
    for (int kk = 0; kk < 2; kk++) {
        __syncthreads();  // Bs/a_s ready (kk=0); Ts consumed by previous phase (kk=1)
        // Ts[ii][j] <- T[k0+kk][i0+ii][jt*128 + j]
#pragma unroll
        for (int l = 0; l < 8; l++) {
            int idx = l * 256 + tid;        // 0..2047
            int ii = idx >> 5, j4 = idx & 31;
            *(float4*)&Ts[ii][j4 * 4] =
                *(const float4*)&d_T[((size_t)((k0 + kk) * SS + i0 + ii)) * SS + jt * 128 + j4 * 4];
        }
        __syncthreads();
#pragma unroll 8
        for (int ii = 0; ii < 64; ii++) {
            ulonglong2 b01 = *(const ulonglong2*)&Bs[ii][w * 8];       // bel n..n+3 (2 pairs)
            ulonglong2 b23 = *(const ulonglong2*)&Bs[ii][w * 8 + 4];   // bel n+4..n+7
            float4 tv = *(const float4*)&Ts[ii][lane * 4];
            unsigned long long t0 = pack2(tv.x), t1 = pack2(tv.y),
                               t2 = pack2(tv.z), t3 = pack2(tv.w);
            fma2(acc[kk][0][0], b01.x, t0); fma2(acc[kk][0][1], b01.x, t1);
            fma2(acc[kk][0][2], b01.x, t2); fma2(acc[kk][0][3], b01.x, t3);
            fma2(acc[kk][1][0], b01.y, t0); fma2(acc[kk][1][1], b01.y, t1);
            fma2(acc[kk][1][2], b01.y, t2); fma2(acc[kk][1][3], b01.y, t3);
            fma2(acc[kk][2][0], b23.x, t0); fma2(acc[kk][2][1], b23.x, t1);
            fma2(acc[kk][2][2], b23.x, t2); fma2(acc[kk][2][3], b23.x, t3);
            fma2(acc[kk][3][0], b23.y, t0); fma2(acc[kk][3][1], b23.y, t1);
            fma2(acc[kk][3][2], b23.y, t2); fma2(acc[kk][3][3], b23.y, t3);
        }
    }

    // epilogue: combine k-pair with a-weights, write one partial slice
    int c = kp * 8 + iz;
#pragma unroll
    for (int p = 0; p < 4; p++) {
#pragma unroll
        for (int par = 0; par < 2; par++) {
            int n = w * 8 + p * 2 + par;
            float a0 = a_s[0][n], a1 = a_s[1][n];
            float4 o;
#pragma unroll
            for (int j = 0; j < 4; j++) {
                float2 f0 = *(float2*)&acc[0][p][j];
                float2 f1 = *(float2*)&acc[1][p][j];
                float v0 = par ? f0.y : f0.x;
                float v1 = par ? f1.y : f1.x;
                ((float*)&o)[j] = v0 * a0 + v1 * a1;
            }
            *(float4*)&d_partial[((size_t)c * BB + n) * SS + jt * 128 + lane * 4] = o;
        }
    }
}

// ---------------- per-step kernel 2: reduce partials + posterior softmax ----------------
// grid = 64 (one per n), 512 threads
__global__ void k_post(const float* __restrict__ lo_t, float* __restrict__ ab_t) {
    __shared__ float buf[16];
    int n = blockIdx.x, j = threadIdx.x;
    float s = 0.f;
#pragma unroll
    for (int c = 0; c < 64; c++) s += d_partial[((size_t)c * BB + n) * SS + j];
    float val = __logf(s + EPSV) + lo_t[n * SS + j];
    float m = bmax512(val, buf);
    float e = __expf(val - m);
    float sum = bsum512(e, buf);
    ab_t[n * SS + j] = e / sum;
}

// ---------------- batched plan (hoisted out of the sequential chain) ----------------
#define PLAN_SMEM (3 * 64 * 68 * 4)
__global__ __launch_bounds__(256, 4) void k_plan(const float* __restrict__ alpha_b,
                                                 const float* __restrict__ value) {
    extern __shared__ char sm[];
    float(*Vs)[68] = (float(*)[68])sm;
    float(*Bs)[68] = (float(*)[68])(sm + 64 * 68 * 4);
    float(*lg)[68] = (float(*)[68])(sm + 2 * 64 * 68 * 4);

    int n = blockIdx.x, hs = blockIdx.y;
    int h0 = hs * 4;
    int tid = threadIdx.x;
    int tx = tid & 15;   // row group: row0 = tx*4 (row = hh*16+kk)
    int ty = tid >> 4;   // t group:   t0 = ty*4

    unsigned long long acc[4][2];
#pragma unroll
    for (int a = 0; a < 4; a++) { acc[a][0] = 0ull; acc[a][1] = 0ull; }

    for (int c = 0; c < 8; c++) {
        int i0 = c * 64;
#pragma unroll
        for (int l = 0; l < 4; l++) {
            int idx = l * 256 + tid;
            int ii = idx & 63, r4 = idx >> 6;
            float4 vv;
#pragma unroll
            for (int q = 0; q < 4; q++) {
                int row = r4 * 4 + q;
                int hh = row >> 4, kk = row & 15;
                ((float*)&vv)[q] = value[(((size_t)(h0 + hh) * BB + n) * AA + kk) * SS + i0 + ii];
            }
            *(float4*)&Vs[ii][r4 * 4] = vv;
        }
#pragma unroll
        for (int l = 0; l < 4; l++) {
            int idx = l * 256 + tid;
            int ii = idx & 63, t4 = idx >> 6;
            float4 bv;
            bv.x = alpha_b[((size_t)(t4 * 4 + 0) * BB + n) * SS + i0 + ii];
            bv.y = alpha_b[((size_t)(t4 * 4 + 1) * BB + n) * SS + i0 + ii];
            bv.z = alpha_b[((size_t)(t4 * 4 + 2) * BB + n) * SS + i0 + ii];
            bv.w = alpha_b[((size_t)(t4 * 4 + 3) * BB + n) * SS + i0 + ii];
            *(float4*)&Bs[ii][t4 * 4] = bv;
        }
        __syncthreads();
#pragma unroll 8
        for (int ii = 0; ii < 64; ii++) {
            ulonglong2 vv = *(const ulonglong2*)&Vs[ii][tx * 4];
            float4 bv = *(const float4*)&Bs[ii][ty * 4];
            unsigned long long b0 = pack2(bv.x), b1 = pack2(bv.y),
                               b2 = pack2(bv.z), b3 = pack2(bv.w);
            fma2(acc[0][0], b0, vv.x); fma2(acc[0][1], b0, vv.y);
            fma2(acc[1][0], b1, vv.x); fma2(acc[1][1], b1, vv.y);
            fma2(acc[2][0], b2, vv.x); fma2(acc[2][1], b2, vv.y);
            fma2(acc[3][0], b3, vv.x); fma2(acc[3][1], b3, vv.y);
        }
        __syncthreads();
    }
#pragma unroll
    for (int tt = 0; tt < 4; tt++) {
        int t = ty * 4 + tt;
        float2 f0 = *(float2*)&acc[tt][0];
        float2 f1 = *(float2*)&acc[tt][1];
        lg[t][tx * 4] = f0.x;
        lg[t][tx * 4 + 1] = f0.y;
        lg[t][tx * 4 + 2] = f1.x;
        lg[t][tx * 4 + 3] = f1.y;
    }
    __syncthreads();

    {
        int t = tid >> 2, hh = tid & 3;
        const float* row = &lg[t][hh * 16];
        float mm = -3.402823466e38f;
#pragma unroll
        for (int k = 0; k < AA; k++) mm = fmaxf(mm, row[k]);
        float ex[AA], se = 0.f;
#pragma unroll
        for (int k = 0; k < AA; k++) { ex[k] = __expf(row[k] - mm); se += ex[k]; }
        float tw = d_taupdf[h0 + hh] / se;
        float pv[AA];
#pragma unroll
        for (int k = 0; k < AA; k++) pv[k] = ex[k] * tw;
#pragma unroll
        for (int k = 0; k < AA; k++) {
            pv[k] += __shfl_xor_sync(0xffffffffu, pv[k], 1);
            pv[k] += __shfl_xor_sync(0xffffffffu, pv[k], 2);
        }
        float* op = &d_pi_part[(((size_t)hs * TT + t) * BB + n) * AA];
#pragma unroll
        for (int q = 0; q < 4; q++) op[hh * 4 + q] = pv[hh * 4 + q];
    }
}

// sum the 8 h-split partials -> alpha_pi.  grid 256 x 256
__global__ void k_pisum(float* __restrict__ api) {
    int idx = blockIdx.x * 256 + threadIdx.x;  // < T*B*A = 65536
    float s = 0.f;
#pragma unroll
    for (int hs = 0; hs < 8; hs++) s += d_pi_part[(size_t)hs * TT * BB * AA + idx];
    api[idx] = s;
}

// ---------------- launch ----------------
extern "C" void kernel_launch(void* const* d_in, const int* in_sizes, int n_in,
                              void* d_out, int out_size) {
    const float* logp_o = (const float*)d_in[0];  // [T,B,S]
    const float* logp_u = (const float*)d_in[1];  // [T,B,A]
    const float* value  = (const float*)d_in[2];  // [H,B,A,S]
    const float* b      = (const float*)d_in[3];  // [B,S]
    const float* u      = (const float*)d_in[4];  // [S,R]
    const float* v      = (const float*)d_in[5];  // [A,R]
    const float* tau    = (const float*)d_in[6];  // [1,1]

    float* out = (float*)d_out;
    float* alpha_b  = out;                          // [T,B,S]
    float* alpha_pi = out + (size_t)TT * BB * SS;   // [T,B,A]

    cudaFuncSetAttribute(k_gemm, cudaFuncAttributeMaxDynamicSharedMemorySize, GEMM_SMEM);
    cudaFuncSetAttribute(k_plan, cudaFuncAttributeMaxDynamicSharedMemorySize, PLAN_SMEM);

    k_pre1<<<528, 512>>>(u, v);
    k_pre2<<<17, 256>>>(logp_u, tau);
    k_trans<<<AA * SS, 512>>>();

    for (int t = 0; t < TT; t++) {
        const float* bel = (t == 0) ? b : (alpha_b + (size_t)(t - 1) * BB * SS);
        dim3 g1(4, 8, 8);
        k_gemm<<<g1, 256, GEMM_SMEM>>>(bel, t);
        k_post<<<BB, 512>>>(logp_o + (size_t)t * BB * SS, alpha_b + (size_t)t * BB * SS);
    }

    dim3 gp(BB, 8);
    k_plan<<<gp, 256, PLAN_SMEM>>>(alpha_b, value);
    k_pisum<<<256, 256>>>(alpha_pi);
}

// round 13
// speedup vs baseline: 3.5835x; 1.4068x over previous
#include <cuda_runtime.h>
#include <cuda_bf16.h>
#include <math.h>
#include <stdint.h>

#define TT 64
#define BB 64
#define SS 512
#define AA 16
#define RR 64
#define HH 32
#define KI 8192
#define EPSV 1e-6f

// ---------------- scratch (no allocations allowed) ----------------
__device__ float d_T[AA * SS * SS];            // transition [k][i][j] (16.8 MB)
__device__ float d_G[SS * SS];
__device__ float d_p[AA * SS];
__device__ float d_alpha_a[TT * BB * AA];
__device__ float d_taupdf[HH];
__device__ float d_partial[32 * BB * SS];      // split-K partials [ks][n][j] (4 MB)
__device__ float d_pi_part[8 * TT * BB * AA];
__device__ __align__(16) __nv_bfloat16 d_Tt_hi[SS * KI];  // T^T, bf16 hi (8 MB)
__device__ __align__(16) __nv_bfloat16 d_Tt_lo[SS * KI];  // residual      (8 MB)
__device__ __align__(16) __nv_bfloat16 d_ab_hi[BB * KI];  // Ã hi (1 MB)
__device__ __align__(16) __nv_bfloat16 d_ab_lo[BB * KI];

// ---------------- generic helpers ----------------
__device__ __forceinline__ void fma2(unsigned long long& d, unsigned long long a,
                                     unsigned long long b) {
    asm("fma.rn.f32x2 %0, %1, %2, %0;" : "+l"(d) : "l"(a), "l"(b));
}
__device__ __forceinline__ unsigned long long pack2(float x) {
    unsigned long long r;
    unsigned int xi = __float_as_uint(x);
    asm("mov.b64 %0, {%1, %1};" : "=l"(r) : "r"(xi));
    return r;
}
__device__ __forceinline__ float bmax512(float v, float* buf) {
    int lane = threadIdx.x & 31, w = threadIdx.x >> 5;
#pragma unroll
    for (int o = 16; o; o >>= 1) v = fmaxf(v, __shfl_xor_sync(0xffffffffu, v, o));
    if (!lane) buf[w] = v;
    __syncthreads();
    if (w == 0) {
        float x = (lane < 16) ? buf[lane] : -3.402823466e38f;
#pragma unroll
        for (int o = 8; o; o >>= 1) x = fmaxf(x, __shfl_xor_sync(0xffffffffu, x, o));
        if (!lane) buf[0] = x;
    }
    __syncthreads();
    float r = buf[0];
    __syncthreads();
    return r;
}
__device__ __forceinline__ float bsum512(float v, float* buf) {
    int lane = threadIdx.x & 31, w = threadIdx.x >> 5;
#pragma unroll
    for (int o = 16; o; o >>= 1) v += __shfl_xor_sync(0xffffffffu, v, o);
    if (!lane) buf[w] = v;
    __syncthreads();
    if (w == 0) {
        float x = (lane < 16) ? buf[lane] : 0.0f;
#pragma unroll
        for (int o = 8; o; o >>= 1) x += __shfl_xor_sync(0xffffffffu, x, o);
        if (!lane) buf[0] = x;
    }
    __syncthreads();
    float r = buf[0];
    __syncthreads();
    return r;
}

// ---------------- HMMA helpers (baseline sm_80+ PTX, legal on sm_103) ----------------
__device__ __forceinline__ uint32_t smem_u32(const void* p) {
    uint32_t a;
    asm("{ .reg .u64 t; cvta.to.shared.u64 t, %1; cvt.u32.u64 %0, t; }" : "=r"(a) : "l"(p));
    return a;
}
__device__ __forceinline__ void ldsm_x4(uint32_t* r, uint32_t addr) {
    asm volatile("ldmatrix.sync.aligned.m8n8.x4.shared.b16 {%0,%1,%2,%3}, [%4];"
                 : "=r"(r[0]), "=r"(r[1]), "=r"(r[2]), "=r"(r[3]) : "r"(addr));
}
__device__ __forceinline__ void mma_bf16(float* d, const uint32_t* a, uint32_t b0, uint32_t b1) {
    asm volatile(
        "mma.sync.aligned.m16n8k16.row.col.f32.bf16.bf16.f32 "
        "{%0,%1,%2,%3}, {%4,%5,%6,%7}, {%8,%9}, {%0,%1,%2,%3};"
        : "+f"(d[0]), "+f"(d[1]), "+f"(d[2]), "+f"(d[3])
        : "r"(a[0]), "r"(a[1]), "r"(a[2]), "r"(a[3]), "r"(b0), "r"(b1));
}

// ---------------- precompute 1: gram + p ----------------
__global__ void k_pre1(const float* __restrict__ u, const float* __restrict__ v) {
    if (blockIdx.x < 512) {
        __shared__ float ui[RR];
        int i = blockIdx.x;
        if (threadIdx.x < RR) ui[threadIdx.x] = u[i * RR + threadIdx.x];
        __syncthreads();
        int j = threadIdx.x;
        const float* uj = u + j * RR;
        float s = 0.f;
#pragma unroll
        for (int r = 0; r < RR; r++) s += ui[r] * uj[r];
        d_G[i * SS + j] = s;
    } else {
        __shared__ float vk[RR];
        __shared__ float invn;
        int k = blockIdx.x - 512, tid = threadIdx.x;
        if (tid < RR) vk[tid] = v[k * RR + tid];
        __syncthreads();
        if (tid == 0) {
            float s = 0.f;
            for (int r = 0; r < RR; r++) s += vk[r] * vk[r];
            invn = rsqrtf(s);
        }
        __syncthreads();
        const float* ui = u + tid * RR;
        float dot = 0.f;
#pragma unroll
        for (int r = 0; r < RR; r++) dot += ui[r] * vk[r];
        d_p[k * SS + tid] = dot * invn;
    }
}

// ---------------- precompute 2: alpha_a + tau ----------------
__global__ void k_pre2(const float* __restrict__ logp_u, const float* __restrict__ tau) {
    if (blockIdx.x < 16) {
        int row = blockIdx.x * 256 + threadIdx.x;
        const float* r = logp_u + row * AA;
        float m = -3.402823466e38f;
#pragma unroll
        for (int k = 0; k < AA; k++) m = fmaxf(m, r[k]);
        float e[AA], s = 0.f;
#pragma unroll
        for (int k = 0; k < AA; k++) { e[k] = expf(r[k] - m); s += e[k]; }
        float inv = 1.0f / s;
        float* o = d_alpha_a + row * AA;
#pragma unroll
        for (int k = 0; k < AA; k++) o[k] = e[k] * inv;
    } else if (threadIdx.x < HH) {
        int h = threadIdx.x;
        float rate = log1pf(expf(tau[0]));
        float lp = (float)(h + 1) * logf(rate) - rate - lgammaf((float)(h + 2));
        float p = expf(lp);
        float s = p;
#pragma unroll
        for (int o = 16; o; o >>= 1) s += __shfl_xor_sync(0xffffffffu, s, o);
        d_taupdf[h] = p / s;
    }
}

// ---------------- transition softmax ----------------
__global__ void k_trans() {
    __shared__ float buf[16];
    int ki = blockIdx.x;
    int k = ki >> 9, i = ki & 511;
    int j = threadIdx.x;
    float pki = d_p[k * SS + i];
    float w = d_G[i * SS + j] - 2.0f * pki * d_p[k * SS + j];
    float m = bmax512(w, buf);
    float e = __expf(w - m);
    float s = bsum512(e, buf);
    d_T[(size_t)ki * SS + j] = e / s;
}

// ---------------- transpose + bf16 split: Tt[j][k*512+i] = T[k][i][j] ----------------
// grid (8 jb, 8 it, 16 k), 256 threads
__global__ void k_tpose() {
    __shared__ float tile[64][65];
    int jb = blockIdx.x, it = blockIdx.y, k = blockIdx.z;
    int tid = threadIdx.x;
#pragma unroll
    for (int l = 0; l < 16; l++) {
        int idx = l * 256 + tid;
        int r = idx >> 6, c = idx & 63;
        tile[r][c] = d_T[((size_t)(k * SS + it * 64 + r)) * SS + jb * 64 + c];
    }
    __syncthreads();
#pragma unroll
    for (int l = 0; l < 16; l++) {
        int idx = l * 256 + tid;
        int r = idx >> 6, c = idx & 63;
        float x = tile[c][r];  // = T[k][it*64+c][jb*64+r]
        __nv_bfloat16 hi = __float2bfloat16(x);
        __nv_bfloat16 lo = __float2bfloat16(x - __bfloat162float(hi));
        size_t o = (size_t)(jb * 64 + r) * KI + k * SS + it * 64 + c;
        d_Tt_hi[o] = hi;
        d_Tt_lo[o] = lo;
    }
}

// ---------------- Ã for t=0 ----------------
__global__ void k_abel0(const float* __restrict__ b) {
    __shared__ float a_s[AA];
    int n = blockIdx.x, j = threadIdx.x;
    if (j < AA) a_s[j] = d_alpha_a[n * AA + j];
    __syncthreads();
    float bel = b[n * SS + j];
#pragma unroll
    for (int k = 0; k < AA; k++) {
        float x = a_s[k] * bel;
        __nv_bfloat16 hi = __float2bfloat16(x);
        __nv_bfloat16 lo = __float2bfloat16(x - __bfloat162float(hi));
        d_ab_hi[(size_t)n * KI + k * SS + j] = hi;
        d_ab_lo[(size_t)n * KI + k * SS + j] = lo;
    }
}

// ---------------- per-step HMMA GEMM: D[j,n] = Tt @ Ã^T, split-K 32 ----------------
// grid (4 jt, 32 ks), 256 threads (8 warps), 1 CTA/SM (192 KB smem), one wave.
// Warp w: j in [16w, 16w+16), all 64 n (8 mma tiles). K window = 256 (16 k16-steps).
// 3-term bf16 compensation: hihi + hilo + lohi into one f32 accumulator set.
#define S_AHI 0
#define S_ALO 65536
#define S_BHI 131072
#define S_BLO 163840
#define MMA_SMEM 196608
// smem rows: 256 bf16 = 512 B. Swizzle: 16B-chunk column byte c ^= (row&7)<<4.

__global__ __launch_bounds__(256, 1) void k_mma() {
    extern __shared__ __align__(128) char sm[];
    uint32_t sb = smem_u32(sm);
    int tid = threadIdx.x, w = tid >> 5, lane = tid & 31;
    int jt = blockIdx.x, ks = blockIdx.y;
    int j0 = jt * 128;
    int ki0 = ks * 256;

    // ---- global -> smem (swizzled), A: 128x256 hi+lo, B: 64x256 hi+lo ----
    {
        const uint4* gAh = (const uint4*)d_Tt_hi;
        const uint4* gAl = (const uint4*)d_Tt_lo;
#pragma unroll
        for (int l = 0; l < 16; l++) {
            int idx = l * 256 + tid;          // 0..4095
            int r = idx >> 5, c = idx & 31;   // row, 16B chunk
            size_t gi = (size_t)(j0 + r) * (KI / 8) + (ki0 >> 3) + c;
            uint32_t so = (uint32_t)(r * 512 + ((c * 16) ^ ((r & 7) << 4)));
            *(uint4*)(sm + S_AHI + so) = gAh[gi];
            *(uint4*)(sm + S_ALO + so) = gAl[gi];
        }
        const uint4* gBh = (const uint4*)d_ab_hi;
        const uint4* gBl = (const uint4*)d_ab_lo;
#pragma unroll
        for (int l = 0; l < 8; l++) {
            int idx = l * 256 + tid;          // 0..2047
            int r = idx >> 5, c = idx & 31;
            size_t gi = (size_t)r * (KI / 8) + (ki0 >> 3) + c;
            uint32_t so = (uint32_t)(r * 512 + ((c * 16) ^ ((r & 7) << 4)));
            *(uint4*)(sm + S_BHI + so) = gBh[gi];
            *(uint4*)(sm + S_BLO + so) = gBl[gi];
        }
    }
    __syncthreads();

    float acc[8][4];
#pragma unroll
    for (int t = 0; t < 8; t++)
#pragma unroll
        for (int q = 0; q < 4; q++) acc[t][q] = 0.f;

    int r = lane & 7, sub = lane >> 3;
    // A ldmatrix.x4: m0=(row r, k-lo), m1=(r+8, k-lo), m2=(r, k-hi), m3=(r+8, k-hi)
    int arow = 16 * w + r + ((sub & 1) << 3);
    uint32_t a_off = (uint32_t)(arow * 512);
    int acol16 = (sub & 2) << 3;  // 0 or 16 bytes
    uint32_t axor = (uint32_t)(r << 4);
    // B ldmatrix.x4 group q: m0=(tile 2q, k-lo), m1=(tile 2q, k-hi), m2/m3 = tile 2q+1
    int bcol16 = (sub & 1) << 4;
    int brow_base = ((sub >> 1) << 3) + r;  // +8 rows for sub 2,3

#pragma unroll 4
    for (int s = 0; s < 16; s++) {
        uint32_t ah[4], al[4], bh[16], bl[16];
        uint32_t ac = ((uint32_t)(32 * s + acol16)) ^ axor;
        ldsm_x4(ah, sb + S_AHI + a_off + ac);
        ldsm_x4(al, sb + S_ALO + a_off + ac);
        uint32_t bc = ((uint32_t)(32 * s + bcol16)) ^ axor;
#pragma unroll
        for (int q = 0; q < 4; q++) {
            uint32_t bo = (uint32_t)((16 * q + brow_base) * 512) + bc;
            ldsm_x4(bh + 4 * q, sb + S_BHI + bo);
            ldsm_x4(bl + 4 * q, sb + S_BLO + bo);
        }
#pragma unroll
        for (int t = 0; t < 8; t++) {
            int base = 4 * (t >> 1) + (t & 1) * 2;
            mma_bf16(acc[t], ah, bh[base], bh[base + 1]);  // hi*hi
            mma_bf16(acc[t], ah, bl[base], bl[base + 1]);  // hi*lo
            mma_bf16(acc[t], al, bh[base], bh[base + 1]);  // lo*hi
        }
    }

    // ---- epilogue: lane holds (j=16w+(lane>>2), n=8t+2(lane&3)) + (j+8, n+1) ----
    int jl = 16 * w + (lane >> 2);
    int nb = 2 * (lane & 3);
#pragma unroll
    for (int t = 0; t < 8; t++) {
        int n = 8 * t + nb;
        float* p0 = &d_partial[((size_t)ks * BB + n) * SS + j0 + jl];
        p0[0] = acc[t][0];       // (j,   n)
        p0[SS] = acc[t][1];      // (j,   n+1)
        p0[8] = acc[t][2];       // (j+8, n)
        p0[SS + 8] = acc[t][3];  // (j+8, n+1)
    }
}

// ---------------- reduce partials + posterior softmax + produce Ã(t+1) ----------------
// grid = 64 (one per n), 512 threads
__global__ void k_post(const float* __restrict__ lo_t, float* __restrict__ ab_t, int t) {
    __shared__ float buf[16];
    __shared__ float a_s[AA];
    int n = blockIdx.x, j = threadIdx.x;
    int has_next = (t + 1 < TT);
    if (j < AA && has_next) a_s[j] = d_alpha_a[(size_t)(t + 1) * BB * AA + n * AA + j];
    float s = 0.f;
#pragma unroll
    for (int c = 0; c < 32; c++) s += d_partial[((size_t)c * BB + n) * SS + j];
    float val = __logf(s + EPSV) + lo_t[n * SS + j];
    float m = bmax512(val, buf);
    float e = __expf(val - m);
    float sum = bsum512(e, buf);
    float b = e / sum;
    ab_t[n * SS + j] = b;
    if (has_next) {
#pragma unroll
        for (int k = 0; k < AA; k++) {
            float x = a_s[k] * b;
            __nv_bfloat16 hi = __float2bfloat16(x);
            __nv_bfloat16 lo = __float2bfloat16(x - __bfloat162float(hi));
            d_ab_hi[(size_t)n * KI + k * SS + j] = hi;
            d_ab_lo[(size_t)n * KI + k * SS + j] = lo;
        }
    }
}

// ---------------- batched plan (outside the sequential chain) ----------------
#define PLAN_SMEM (3 * 64 * 68 * 4)
__global__ __launch_bounds__(256, 4) void k_plan(const float* __restrict__ alpha_b,
                                                 const float* __restrict__ value) {
    extern __shared__ char sm[];
    float(*Vs)[68] = (float(*)[68])sm;
    float(*Bs)[68] = (float(*)[68])(sm + 64 * 68 * 4);
    float(*lg)[68] = (float(*)[68])(sm + 2 * 64 * 68 * 4);

    int n = blockIdx.x, hs = blockIdx.y;
    int h0 = hs * 4;
    int tid = threadIdx.x;
    int tx = tid & 15;
    int ty = tid >> 4;

    unsigned long long acc[4][2];
#pragma unroll
    for (int a = 0; a < 4; a++) { acc[a][0] = 0ull; acc[a][1] = 0ull; }

    for (int c = 0; c < 8; c++) {
        int i0 = c * 64;
#pragma unroll
        for (int l = 0; l < 4; l++) {
            int idx = l * 256 + tid;
            int ii = idx & 63, r4 = idx >> 6;
            float4 vv;
#pragma unroll
            for (int q = 0; q < 4; q++) {
                int row = r4 * 4 + q;
                int hh = row >> 4, kk = row & 15;
                ((float*)&vv)[q] = value[(((size_t)(h0 + hh) * BB + n) * AA + kk) * SS + i0 + ii];
            }
            *(float4*)&Vs[ii][r4 * 4] = vv;
        }
#pragma unroll
        for (int l = 0; l < 4; l++) {
            int idx = l * 256 + tid;
            int ii = idx & 63, t4 = idx >> 6;
            float4 bv;
            bv.x = alpha_b[((size_t)(t4 * 4 + 0) * BB + n) * SS + i0 + ii];
            bv.y = alpha_b[((size_t)(t4 * 4 + 1) * BB + n) * SS + i0 + ii];
            bv.z = alpha_b[((size_t)(t4 * 4 + 2) * BB + n) * SS + i0 + ii];
            bv.w = alpha_b[((size_t)(t4 * 4 + 3) * BB + n) * SS + i0 + ii];
            *(float4*)&Bs[ii][t4 * 4] = bv;
        }
        __syncthreads();
#pragma unroll 8
        for (int ii = 0; ii < 64; ii++) {
            ulonglong2 vv = *(const ulonglong2*)&Vs[ii][tx * 4];
            float4 bv = *(const float4*)&Bs[ii][ty * 4];
            unsigned long long b0 = pack2(bv.x), b1 = pack2(bv.y),
                               b2 = pack2(bv.z), b3 = pack2(bv.w);
            fma2(acc[0][0], b0, vv.x); fma2(acc[0][1], b0, vv.y);
            fma2(acc[1][0], b1, vv.x); fma2(acc[1][1], b1, vv.y);
            fma2(acc[2][0], b2, vv.x); fma2(acc[2][1], b2, vv.y);
            fma2(acc[3][0], b3, vv.x); fma2(acc[3][1], b3, vv.y);
        }
        __syncthreads();
    }
#pragma unroll
    for (int tt = 0; tt < 4; tt++) {
        int t = ty * 4 + tt;
        float2 f0 = *(float2*)&acc[tt][0];
        float2 f1 = *(float2*)&acc[tt][1];
        lg[t][tx * 4] = f0.x;
        lg[t][tx * 4 + 1] = f0.y;
        lg[t][tx * 4 + 2] = f1.x;
        lg[t][tx * 4 + 3] = f1.y;
    }
    __syncthreads();
    {
        int t = tid >> 2, hh = tid & 3;
        const float* row = &lg[t][hh * 16];
        float mm = -3.402823466e38f;
#pragma unroll
        for (int k = 0; k < AA; k++) mm = fmaxf(mm, row[k]);
        float ex[AA], se = 0.f;
#pragma unroll
        for (int k = 0; k < AA; k++) { ex[k] = __expf(row[k] - mm); se += ex[k]; }
        float tw = d_taupdf[h0 + hh] / se;
        float pv[AA];
#pragma unroll
        for (int k = 0; k < AA; k++) pv[k] = ex[k] * tw;
#pragma unroll
        for (int k = 0; k < AA; k++) {
            pv[k] += __shfl_xor_sync(0xffffffffu, pv[k], 1);
            pv[k] += __shfl_xor_sync(0xffffffffu, pv[k], 2);
        }
        float* op = &d_pi_part[(((size_t)hs * TT + t) * BB + n) * AA];
#pragma unroll
        for (int q = 0; q < 4; q++) op[hh * 4 + q] = pv[hh * 4 + q];
    }
}

__global__ void k_pisum(float* __restrict__ api) {
    int idx = blockIdx.x * 256 + threadIdx.x;
    float s = 0.f;
#pragma unroll
    for (int hs = 0; hs < 8; hs++) s += d_pi_part[(size_t)hs * TT * BB * AA + idx];
    api[idx] = s;
}

// ---------------- launch ----------------
extern "C" void kernel_launch(void* const* d_in, const int* in_sizes, int n_in,
                              void* d_out, int out_size) {
    const float* logp_o = (const float*)d_in[0];
    const float* logp_u = (const float*)d_in[1];
    const float* value  = (const float*)d_in[2];
    const float* b      = (const float*)d_in[3];
    const float* u      = (const float*)d_in[4];
    const float* v      = (const float*)d_in[5];
    const float* tau    = (const float*)d_in[6];

    float* out = (float*)d_out;
    float* alpha_b  = out;                         // [T,B,S]
    float* alpha_pi = out + (size_t)TT * BB * SS;  // [T,B,A]

    cudaFuncSetAttribute(k_mma, cudaFuncAttributeMaxDynamicSharedMemorySize, MMA_SMEM);
    cudaFuncSetAttribute(k_plan, cudaFuncAttributeMaxDynamicSharedMemorySize, PLAN_SMEM);

    k_pre1<<<528, 512>>>(u, v);
    k_pre2<<<17, 256>>>(logp_u, tau);
    k_trans<<<AA * SS, 512>>>();
    {
        dim3 gt(8, 8, 16);
        k_tpose<<<gt, 256>>>();
    }
    k_abel0<<<BB, 512>>>(b);

    for (int t = 0; t < TT; t++) {
        dim3 gm(4, 32);
        k_mma<<<gm, 256, MMA_SMEM>>>();
        k_post<<<BB, 512>>>(logp_o + (size_t)t * BB * SS,
                            alpha_b + (size_t)t * BB * SS, t);
    }

    dim3 gp(BB, 8);
    k_plan<<<gp, 256, PLAN_SMEM>>>(alpha_b, value);
    k_pisum<<<256, 256>>>(alpha_pi);
}

// round 14
// speedup vs baseline: 4.6926x; 1.3095x over previous
#include <cuda_runtime.h>
#include <cuda_fp16.h>
#include <math.h>
#include <stdint.h>

#define TT 64
#define BB 64
#define SS 512
#define AA 16
#define RR 64
#define HH 32
#define KI 8192
#define EPSV 1e-6f

// ---------------- scratch (no allocations allowed) ----------------
__device__ float d_T[AA * SS * SS];            // transition [k][i][j] (16.8 MB)
__device__ float d_G[SS * SS];
__device__ float d_p[AA * SS];
__device__ float d_alpha_a[TT * BB * AA];
__device__ float d_taupdf[HH];
__device__ float d_partial[32 * BB * SS];      // split-K partials [ks][n][j] (4 MB)
__device__ float d_pi_part[8 * TT * BB * AA];
__device__ __align__(16) __half d_Tt_hi[SS * KI];  // T^T fp16 hi (8 MB)
__device__ __align__(16) __half d_Tt_lo[SS * KI];  // fp16 residual (8 MB)
__device__ __align__(16) __half d_ab[BB * KI];     // Ã = a⊗bel, fp16 (1 MB)
__device__ unsigned int g_cnt;                      // grid barrier counter

// ---------------- generic helpers ----------------
__device__ __forceinline__ void fma2(unsigned long long& d, unsigned long long a,
                                     unsigned long long b) {
    asm("fma.rn.f32x2 %0, %1, %2, %0;" : "+l"(d) : "l"(a), "l"(b));
}
__device__ __forceinline__ unsigned long long pack2(float x) {
    unsigned long long r;
    unsigned int xi = __float_as_uint(x);
    asm("mov.b64 %0, {%1, %1};" : "=l"(r) : "r"(xi));
    return r;
}
// block reduce over nw warps (nw <= 16), buf >= nw floats
__device__ __forceinline__ float bmaxN(float v, float* buf, int nw) {
    int lane = threadIdx.x & 31, w = threadIdx.x >> 5;
#pragma unroll
    for (int o = 16; o; o >>= 1) v = fmaxf(v, __shfl_xor_sync(0xffffffffu, v, o));
    if (!lane) buf[w] = v;
    __syncthreads();
    if (w == 0) {
        float x = (lane < nw) ? buf[lane] : -3.402823466e38f;
#pragma unroll
        for (int o = 8; o; o >>= 1) x = fmaxf(x, __shfl_xor_sync(0xffffffffu, x, o));
        if (!lane) buf[0] = x;
    }
    __syncthreads();
    float r = buf[0];
    __syncthreads();
    return r;
}
__device__ __forceinline__ float bsumN(float v, float* buf, int nw) {
    int lane = threadIdx.x & 31, w = threadIdx.x >> 5;
#pragma unroll
    for (int o = 16; o; o >>= 1) v += __shfl_xor_sync(0xffffffffu, v, o);
    if (!lane) buf[w] = v;
    __syncthreads();
    if (w == 0) {
        float x = (lane < nw) ? buf[lane] : 0.0f;
#pragma unroll
        for (int o = 8; o; o >>= 1) x += __shfl_xor_sync(0xffffffffu, x, o);
        if (!lane) buf[0] = x;
    }
    __syncthreads();
    float r = buf[0];
    __syncthreads();
    return r;
}

// ---------------- HMMA helpers (sm_80 baseline PTX) ----------------
__device__ __forceinline__ uint32_t smem_u32(const void* p) {
    uint32_t a;
    asm("{ .reg .u64 t; cvta.to.shared.u64 t, %1; cvt.u32.u64 %0, t; }" : "=r"(a) : "l"(p));
    return a;
}
__device__ __forceinline__ void ldsm_x4(uint32_t* r, uint32_t addr) {
    asm volatile("ldmatrix.sync.aligned.m8n8.x4.shared.b16 {%0,%1,%2,%3}, [%4];"
                 : "=r"(r[0]), "=r"(r[1]), "=r"(r[2]), "=r"(r[3]) : "r"(addr));
}
__device__ __forceinline__ void mma_f16(float* d, const uint32_t* a, uint32_t b0, uint32_t b1) {
    asm volatile(
        "mma.sync.aligned.m16n8k16.row.col.f32.f16.f16.f32 "
        "{%0,%1,%2,%3}, {%4,%5,%6,%7}, {%8,%9}, {%0,%1,%2,%3};"
        : "+f"(d[0]), "+f"(d[1]), "+f"(d[2]), "+f"(d[3])
        : "r"(a[0]), "r"(a[1]), "r"(a[2]), "r"(a[3]), "r"(b0), "r"(b1));
}

// grid barrier: all 128 CTAs co-resident (1 CTA/SM, single wave)
__device__ __forceinline__ void grid_bar(unsigned target) {
    __syncthreads();
    if (threadIdx.x == 0) {
        __threadfence();
        atomicAdd(&g_cnt, 1u);
        while (atomicAdd(&g_cnt, 0u) < target) __nanosleep(64);
    }
    __syncthreads();
}

// ---------------- precompute 1: gram + p ----------------
__global__ void k_pre1(const float* __restrict__ u, const float* __restrict__ v) {
    if (blockIdx.x < 512) {
        __shared__ float ui[RR];
        int i = blockIdx.x;
        if (threadIdx.x < RR) ui[threadIdx.x] = u[i * RR + threadIdx.x];
        __syncthreads();
        int j = threadIdx.x;
        const float* uj = u + j * RR;
        float s = 0.f;
#pragma unroll
        for (int r = 0; r < RR; r++) s += ui[r] * uj[r];
        d_G[i * SS + j] = s;
    } else {
        __shared__ float vk[RR];
        __shared__ float invn;
        int k = blockIdx.x - 512, tid = threadIdx.x;
        if (tid < RR) vk[tid] = v[k * RR + tid];
        __syncthreads();
        if (tid == 0) {
            float s = 0.f;
            for (int r = 0; r < RR; r++) s += vk[r] * vk[r];
            invn = rsqrtf(s);
        }
        __syncthreads();
        const float* ui = u + tid * RR;
        float dot = 0.f;
#pragma unroll
        for (int r = 0; r < RR; r++) dot += ui[r] * vk[r];
        d_p[k * SS + tid] = dot * invn;
    }
}

// ---------------- precompute 2: alpha_a + tau ----------------
__global__ void k_pre2(const float* __restrict__ logp_u, const float* __restrict__ tau) {
    if (blockIdx.x < 16) {
        int row = blockIdx.x * 256 + threadIdx.x;
        const float* r = logp_u + row * AA;
        float m = -3.402823466e38f;
#pragma unroll
        for (int k = 0; k < AA; k++) m = fmaxf(m, r[k]);
        float e[AA], s = 0.f;
#pragma unroll
        for (int k = 0; k < AA; k++) { e[k] = expf(r[k] - m); s += e[k]; }
        float inv = 1.0f / s;
        float* o = d_alpha_a + row * AA;
#pragma unroll
        for (int k = 0; k < AA; k++) o[k] = e[k] * inv;
    } else if (threadIdx.x < HH) {
        int h = threadIdx.x;
        float rate = log1pf(expf(tau[0]));
        float lp = (float)(h + 1) * logf(rate) - rate - lgammaf((float)(h + 2));
        float p = expf(lp);
        float s = p;
#pragma unroll
        for (int o = 16; o; o >>= 1) s += __shfl_xor_sync(0xffffffffu, s, o);
        d_taupdf[h] = p / s;
    }
}

// ---------------- transition softmax ----------------
__global__ void k_trans() {
    __shared__ float buf[16];
    int ki = blockIdx.x;
    int k = ki >> 9, i = ki & 511;
    int j = threadIdx.x;
    float pki = d_p[k * SS + i];
    float w = d_G[i * SS + j] - 2.0f * pki * d_p[k * SS + j];
    float m = bmaxN(w, buf, 16);
    float e = __expf(w - m);
    float s = bsumN(e, buf, 16);
    d_T[(size_t)ki * SS + j] = e / s;
}

// ---------------- transpose + fp16 split: Tt[j][k*512+i] = T[k][i][j] ----------------
__global__ void k_tpose() {
    __shared__ float tile[64][65];
    int jb = blockIdx.x, it = blockIdx.y, k = blockIdx.z;
    int tid = threadIdx.x;
#pragma unroll
    for (int l = 0; l < 16; l++) {
        int idx = l * 256 + tid;
        int r = idx >> 6, c = idx & 63;
        tile[r][c] = d_T[((size_t)(k * SS + it * 64 + r)) * SS + jb * 64 + c];
    }
    __syncthreads();
#pragma unroll
    for (int l = 0; l < 16; l++) {
        int idx = l * 256 + tid;
        int r = idx >> 6, c = idx & 63;
        float x = tile[c][r];
        __half hi = __float2half_rn(x);
        __half lo = __float2half_rn(x - __half2float(hi));
        size_t o = (size_t)(jb * 64 + r) * KI + k * SS + it * 64 + c;
        d_Tt_hi[o] = hi;
        d_Tt_lo[o] = lo;
    }
}

// ---------------- Ã for t=0 + barrier counter reset ----------------
__global__ void k_abel0(const float* __restrict__ b) {
    __shared__ float a_s[AA];
    if (blockIdx.x == 0 && threadIdx.x == 0) g_cnt = 0u;
    int n = blockIdx.x, j = threadIdx.x;
    if (j < AA) a_s[j] = d_alpha_a[n * AA + j];
    __syncthreads();
    float bel = b[n * SS + j];
#pragma unroll
    for (int k = 0; k < AA; k++)
        d_ab[(size_t)n * KI + k * SS + j] = __float2half_rn(a_s[k] * bel);
}

// ---------------- persistent scan: 64 x (HMMA GEMM + grid-bar + post + grid-bar) ---
// grid (4 jt, 32 ks) = 128 CTAs (one wave), 256 threads, 1 CTA/SM.
// A tile (Tt hi/lo fp16, 128j x 256ki, swizzled) stays RESIDENT in smem all 64 steps.
// Per step: load B = ab slice (fp16, 64n x 256ki), 2-GEMM compensation (A_hi*B + A_lo*B),
// write split-K partials, barrier, CTAs 0..63 do posterior softmax + produce ab(t+1).
#define S_AHI 0
#define S_ALO 65536
#define S_B   131072
#define S_PB  163840
#define SCAN_SMEM (163840 + 256)

__global__ __launch_bounds__(256, 1) void k_scan(const float* __restrict__ logp_o,
                                                 float* __restrict__ alpha_b) {
    extern __shared__ __align__(128) char sm[];
    uint32_t sb = smem_u32(sm);
    float* buf = (float*)(sm + S_PB);
    float* a_s = buf + 16;
    int tid = threadIdx.x, w = tid >> 5, lane = tid & 31;
    int jt = blockIdx.x, ks = blockIdx.y;
    int cta = ks * 4 + jt;
    int j0 = jt * 128, ki0 = ks * 256;

    // resident A (hi/lo), swizzled: row stride 512 B, 16B chunk c ^= (row&7)<<4
    {
        const uint4* gh = (const uint4*)d_Tt_hi;
        const uint4* gl = (const uint4*)d_Tt_lo;
#pragma unroll
        for (int l = 0; l < 16; l++) {
            int idx = l * 256 + tid;
            int r = idx >> 5, c = idx & 31;
            size_t gi = (size_t)(j0 + r) * (KI / 8) + (ki0 >> 3) + c;
            uint32_t so = (uint32_t)(r * 512 + ((c * 16) ^ ((r & 7) << 4)));
            *(uint4*)(sm + S_AHI + so) = gh[gi];
            *(uint4*)(sm + S_ALO + so) = gl[gi];
        }
    }

    int r8 = lane & 7, sub = lane >> 3;
    int arow = 16 * w + r8 + ((sub & 1) << 3);
    uint32_t a_off = (uint32_t)(arow * 512);
    int acol16 = (sub & 2) << 3;
    uint32_t axor = (uint32_t)(r8 << 4);
    int bcol16 = (sub & 1) << 4;
    int brow_base = ((sub >> 1) << 3) + r8;
    int jl = 16 * w + (lane >> 2);
    int nb = 2 * (lane & 3);

    unsigned bar = 0;

    for (int t = 0; t < TT; t++) {
        // ---- B load (written by previous post on other SMs -> bypass L1 via ldcg) ----
        {
            const uint4* gB = (const uint4*)d_ab;
#pragma unroll
            for (int l = 0; l < 8; l++) {
                int idx = l * 256 + tid;
                int rr = idx >> 5, c = idx & 31;
                uint4 vb = __ldcg(&gB[(size_t)rr * (KI / 8) + (ki0 >> 3) + c]);
                uint32_t so = (uint32_t)(rr * 512 + ((c * 16) ^ ((rr & 7) << 4)));
                *(uint4*)(sm + S_B + so) = vb;
            }
        }
        __syncthreads();

        // ---- MMA: warp w covers j [16w,16w+16), all 64 n; 16 k16-steps, 2 GEMMs ----
        float acc[8][4];
#pragma unroll
        for (int tt = 0; tt < 8; tt++)
#pragma unroll
            for (int q = 0; q < 4; q++) acc[tt][q] = 0.f;

#pragma unroll 4
        for (int s = 0; s < 16; s++) {
            uint32_t ah[4], al[4], bh[16];
            uint32_t ac = ((uint32_t)(32 * s + acol16)) ^ axor;
            ldsm_x4(ah, sb + S_AHI + a_off + ac);
            ldsm_x4(al, sb + S_ALO + a_off + ac);
            uint32_t bc = ((uint32_t)(32 * s + bcol16)) ^ axor;
#pragma unroll
            for (int q = 0; q < 4; q++) {
                uint32_t bo = (uint32_t)((16 * q + brow_base) * 512) + bc;
                ldsm_x4(bh + 4 * q, sb + S_B + bo);
            }
#pragma unroll
            for (int tt = 0; tt < 8; tt++) {
                int base = 4 * (tt >> 1) + (tt & 1) * 2;
                mma_f16(acc[tt], ah, bh[base], bh[base + 1]);  // A_hi * B
                mma_f16(acc[tt], al, bh[base], bh[base + 1]);  // A_lo * B
            }
        }
        // ---- epilogue: split-K partials ----
#pragma unroll
        for (int tt = 0; tt < 8; tt++) {
            int n = 8 * tt + nb;
            float* p0 = &d_partial[((size_t)ks * BB + n) * SS + j0 + jl];
            p0[0] = acc[tt][0];
            p0[SS] = acc[tt][1];
            p0[8] = acc[tt][2];
            p0[SS + 8] = acc[tt][3];
        }

        grid_bar(++bar * 128u);

        // ---- post: CTAs 0..63, n = cta, thread handles j = tid and tid+256 ----
        if (cta < 64) {
            int n = cta;
            if (tid < AA && t + 1 < TT)
                a_s[tid] = d_alpha_a[(size_t)(t + 1) * BB * AA + n * AA + tid];
            float s0 = 0.f, s1 = 0.f;
#pragma unroll
            for (int c = 0; c < 32; c++) {
                const float* pp = &d_partial[((size_t)c * BB + n) * SS];
                s0 += __ldcg(pp + tid);
                s1 += __ldcg(pp + tid + 256);
            }
            const float* lo = logp_o + (size_t)t * BB * SS + (size_t)n * SS;
            float v0 = __logf(s0 + EPSV) + lo[tid];
            float v1 = __logf(s1 + EPSV) + lo[tid + 256];
            float m = bmaxN(fmaxf(v0, v1), buf, 8);
            float e0 = __expf(v0 - m), e1 = __expf(v1 - m);
            float sum = bsumN(e0 + e1, buf, 8);
            float inv = 1.0f / sum;
            float b0 = e0 * inv, b1 = e1 * inv;
            float* abp = alpha_b + (size_t)t * BB * SS + (size_t)n * SS;
            abp[tid] = b0;
            abp[tid + 256] = b1;
            if (t + 1 < TT) {
#pragma unroll
                for (int k = 0; k < AA; k++) {
                    float ak = a_s[k];
                    d_ab[(size_t)n * KI + k * SS + tid] = __float2half_rn(ak * b0);
                    d_ab[(size_t)n * KI + k * SS + tid + 256] = __float2half_rn(ak * b1);
                }
            }
        }
        grid_bar(++bar * 128u);
    }
}

// ---------------- batched plan (outside the sequential chain) ----------------
#define PLAN_SMEM (3 * 64 * 68 * 4)
__global__ __launch_bounds__(256, 4) void k_plan(const float* __restrict__ alpha_b,
                                                 const float* __restrict__ value) {
    extern __shared__ char sm[];
    float(*Vs)[68] = (float(*)[68])sm;
    float(*Bs)[68] = (float(*)[68])(sm + 64 * 68 * 4);
    float(*lg)[68] = (float(*)[68])(sm + 2 * 64 * 68 * 4);

    int n = blockIdx.x, hs = blockIdx.y;
    int h0 = hs * 4;
    int tid = threadIdx.x;
    int tx = tid & 15;
    int ty = tid >> 4;

    unsigned long long acc[4][2];
#pragma unroll
    for (int a = 0; a < 4; a++) { acc[a][0] = 0ull; acc[a][1] = 0ull; }

    for (int c = 0; c < 8; c++) {
        int i0 = c * 64;
#pragma unroll
        for (int l = 0; l < 4; l++) {
            int idx = l * 256 + tid;
            int ii = idx & 63, r4 = idx >> 6;
            float4 vv;
#pragma unroll
            for (int q = 0; q < 4; q++) {
                int row = r4 * 4 + q;
                int hh = row >> 4, kk = row & 15;
                ((float*)&vv)[q] = value[(((size_t)(h0 + hh) * BB + n) * AA + kk) * SS + i0 + ii];
            }
            *(float4*)&Vs[ii][r4 * 4] = vv;
        }
#pragma unroll
        for (int l = 0; l < 4; l++) {
            int idx = l * 256 + tid;
            int ii = idx & 63, t4 = idx >> 6;
            float4 bv;
            bv.x = alpha_b[((size_t)(t4 * 4 + 0) * BB + n) * SS + i0 + ii];
            bv.y = alpha_b[((size_t)(t4 * 4 + 1) * BB + n) * SS + i0 + ii];
            bv.z = alpha_b[((size_t)(t4 * 4 + 2) * BB + n) * SS + i0 + ii];
            bv.w = alpha_b[((size_t)(t4 * 4 + 3) * BB + n) * SS + i0 + ii];
            *(float4*)&Bs[ii][t4 * 4] = bv;
        }
        __syncthreads();
#pragma unroll 8
        for (int ii = 0; ii < 64; ii++) {
            ulonglong2 vv = *(const ulonglong2*)&Vs[ii][tx * 4];
            float4 bv = *(const float4*)&Bs[ii][ty * 4];
            unsigned long long b0 = pack2(bv.x), b1 = pack2(bv.y),
                               b2 = pack2(bv.z), b3 = pack2(bv.w);
            fma2(acc[0][0], b0, vv.x); fma2(acc[0][1], b0, vv.y);
            fma2(acc[1][0], b1, vv.x); fma2(acc[1][1], b1, vv.y);
            fma2(acc[2][0], b2, vv.x); fma2(acc[2][1], b2, vv.y);
            fma2(acc[3][0], b3, vv.x); fma2(acc[3][1], b3, vv.y);
        }
        __syncthreads();
    }
#pragma unroll
    for (int tt = 0; tt < 4; tt++) {
        int t = ty * 4 + tt;
        float2 f0 = *(float2*)&acc[tt][0];
        float2 f1 = *(float2*)&acc[tt][1];
        lg[t][tx * 4] = f0.x;
        lg[t][tx * 4 + 1] = f0.y;
        lg[t][tx * 4 + 2] = f1.x;
        lg[t][tx * 4 + 3] = f1.y;
    }
    __syncthreads();
    {
        int t = tid >> 2, hh = tid & 3;
        const float* row = &lg[t][hh * 16];
        float mm = -3.402823466e38f;
#pragma unroll
        for (int k = 0; k < AA; k++) mm = fmaxf(mm, row[k]);
        float ex[AA], se = 0.f;
#pragma unroll
        for (int k = 0; k < AA; k++) { ex[k] = __expf(row[k] - mm); se += ex[k]; }
        float tw = d_taupdf[h0 + hh] / se;
        float pv[AA];
#pragma unroll
        for (int k = 0; k < AA; k++) pv[k] = ex[k] * tw;
#pragma unroll
        for (int k = 0; k < AA; k++) {
            pv[k] += __shfl_xor_sync(0xffffffffu, pv[k], 1);
            pv[k] += __shfl_xor_sync(0xffffffffu, pv[k], 2);
        }
        float* op = &d_pi_part[(((size_t)hs * TT + t) * BB + n) * AA];
#pragma unroll
        for (int q = 0; q < 4; q++) op[hh * 4 + q] = pv[hh * 4 + q];
    }
}

__global__ void k_pisum(float* __restrict__ api) {
    int idx = blockIdx.x * 256 + threadIdx.x;
    float s = 0.f;
#pragma unroll
    for (int hs = 0; hs < 8; hs++) s += d_pi_part[(size_t)hs * TT * BB * AA + idx];
    api[idx] = s;
}

// ---------------- launch ----------------
extern "C" void kernel_launch(void* const* d_in, const int* in_sizes, int n_in,
                              void* d_out, int out_size) {
    const float* logp_o = (const float*)d_in[0];
    const float* logp_u = (const float*)d_in[1];
    const float* value  = (const float*)d_in[2];
    const float* b      = (const float*)d_in[3];
    const float* u      = (const float*)d_in[4];
    const float* v      = (const float*)d_in[5];
    const float* tau    = (const float*)d_in[6];

    float* out = (float*)d_out;
    float* alpha_b  = out;                         // [T,B,S]
    float* alpha_pi = out + (size_t)TT * BB * SS;  // [T,B,A]

    cudaFuncSetAttribute(k_scan, cudaFuncAttributeMaxDynamicSharedMemorySize, SCAN_SMEM);
    cudaFuncSetAttribute(k_plan, cudaFuncAttributeMaxDynamicSharedMemorySize, PLAN_SMEM);

    k_pre1<<<528, 512>>>(u, v);
    k_pre2<<<17, 256>>>(logp_u, tau);
    k_trans<<<AA * SS, 512>>>();
    {
        dim3 gt(8, 8, 16);
        k_tpose<<<gt, 256>>>();
    }
    k_abel0<<<BB, 512>>>(b);

    {
        dim3 gs(4, 32);
        k_scan<<<gs, 256, SCAN_SMEM>>>(logp_o, alpha_b);
    }

    dim3 gp(BB, 8);
    k_plan<<<gp, 256, PLAN_SMEM>>>(alpha_b, value);
    k_pisum<<<256, 256>>>(alpha_pi);
}

// round 16
// speedup vs baseline: 5.0444x; 1.0750x over previous
#include <cuda_runtime.h>
#include <cuda_fp16.h>
#include <math.h>
#include <stdint.h>

#define TT 64
#define BB 64
#define SS 512
#define AA 16
#define RR 64
#define HH 32
#define KI 8192
#define EPSV 1e-6f

// ---------------- scratch (no allocations allowed) ----------------
__device__ float d_T[AA * SS * SS];            // transition [k][i][j] (16.8 MB)
__device__ float d_G[SS * SS];
__device__ float d_p[AA * SS];
__device__ float d_alpha_a[TT * BB * AA];
__device__ float d_taupdf[HH];
__device__ float d_partial[32 * BB * SS];      // split-K partials [ks][n][j] (4 MB)
__device__ float d_pi_part[8 * TT * BB * AA];
__device__ __align__(16) __half d_Tt[SS * KI];  // T^T fp16 (8 MB)
__device__ __align__(16) __half d_ab[BB * KI];  // Ã = a⊗bel, fp16 (1 MB)
__device__ unsigned int g_cnt;                  // grid barrier counter

// ---------------- generic helpers ----------------
__device__ __forceinline__ void fma2(unsigned long long& d, unsigned long long a,
                                     unsigned long long b) {
    asm("fma.rn.f32x2 %0, %1, %2, %0;" : "+l"(d) : "l"(a), "l"(b));
}
__device__ __forceinline__ unsigned long long pack2(float x) {
    unsigned long long r;
    unsigned int xi = __float_as_uint(x);
    asm("mov.b64 %0, {%1, %1};" : "=l"(r) : "r"(xi));
    return r;
}
// block reduce over nw warps (nw <= 16), buf >= nw floats
__device__ __forceinline__ float bmaxN(float v, float* buf, int nw) {
    int lane = threadIdx.x & 31, w = threadIdx.x >> 5;
#pragma unroll
    for (int o = 16; o; o >>= 1) v = fmaxf(v, __shfl_xor_sync(0xffffffffu, v, o));
    if (!lane) buf[w] = v;
    __syncthreads();
    if (w == 0) {
        float x = (lane < nw) ? buf[lane] : -3.402823466e38f;
#pragma unroll
        for (int o = 8; o; o >>= 1) x = fmaxf(x, __shfl_xor_sync(0xffffffffu, x, o));
        if (!lane) buf[0] = x;
    }
    __syncthreads();
    float r = buf[0];
    __syncthreads();
    return r;
}
__device__ __forceinline__ float bsumN(float v, float* buf, int nw) {
    int lane = threadIdx.x & 31, w = threadIdx.x >> 5;
#pragma unroll
    for (int o = 16; o; o >>= 1) v += __shfl_xor_sync(0xffffffffu, v, o);
    if (!lane) buf[w] = v;
    __syncthreads();
    if (w == 0) {
        float x = (lane < nw) ? buf[lane] : 0.0f;
#pragma unroll
        for (int o = 8; o; o >>= 1) x += __shfl_xor_sync(0xffffffffu, x, o);
        if (!lane) buf[0] = x;
    }
    __syncthreads();
    float r = buf[0];
    __syncthreads();
    return r;
}

// ---------------- HMMA helpers (sm_80 baseline PTX) ----------------
__device__ __forceinline__ uint32_t smem_u32(const void* p) {
    uint32_t a;
    asm("{ .reg .u64 t; cvta.to.shared.u64 t, %1; cvt.u32.u64 %0, t; }" : "=r"(a) : "l"(p));
    return a;
}
__device__ __forceinline__ void ldsm_x4(uint32_t* r, uint32_t addr) {
    asm volatile("ldmatrix.sync.aligned.m8n8.x4.shared.b16 {%0,%1,%2,%3}, [%4];"
                 : "=r"(r[0]), "=r"(r[1]), "=r"(r[2]), "=r"(r[3]) : "r"(addr));
}
__device__ __forceinline__ void mma_f16(float* d, const uint32_t* a, uint32_t b0, uint32_t b1) {
    asm volatile(
        "mma.sync.aligned.m16n8k16.row.col.f32.f16.f16.f32 "
        "{%0,%1,%2,%3}, {%4,%5,%6,%7}, {%8,%9}, {%0,%1,%2,%3};"
        : "+f"(d[0]), "+f"(d[1]), "+f"(d[2]), "+f"(d[3])
        : "r"(a[0]), "r"(a[1]), "r"(a[2]), "r"(a[3]), "r"(b0), "r"(b1));
}

// grid barrier: all 128 CTAs co-resident (1 CTA/SM, single wave)
__device__ __forceinline__ void grid_bar(unsigned target) {
    __syncthreads();
    if (threadIdx.x == 0) {
        __threadfence();
        atomicAdd(&g_cnt, 1u);
        while (atomicAdd(&g_cnt, 0u) < target) __nanosleep(64);
    }
    __syncthreads();
}

// ---------------- precompute 1: gram + p ----------------
__global__ void k_pre1(const float* __restrict__ u, const float* __restrict__ v) {
    if (blockIdx.x < 512) {
        __shared__ float ui[RR];
        int i = blockIdx.x;
        if (threadIdx.x < RR) ui[threadIdx.x] = u[i * RR + threadIdx.x];
        __syncthreads();
        int j = threadIdx.x;
        const float* uj = u + j * RR;
        float s = 0.f;
#pragma unroll
        for (int r = 0; r < RR; r++) s += ui[r] * uj[r];
        d_G[i * SS + j] = s;
    } else {
        __shared__ float vk[RR];
        __shared__ float invn;
        int k = blockIdx.x - 512, tid = threadIdx.x;
        if (tid < RR) vk[tid] = v[k * RR + tid];
        __syncthreads();
        if (tid == 0) {
            float s = 0.f;
            for (int r = 0; r < RR; r++) s += vk[r] * vk[r];
            invn = rsqrtf(s);
        }
        __syncthreads();
        const float* ui = u + tid * RR;
        float dot = 0.f;
#pragma unroll
        for (int r = 0; r < RR; r++) dot += ui[r] * vk[r];
        d_p[k * SS + tid] = dot * invn;
    }
}

// ---------------- precompute 2: alpha_a + tau ----------------
__global__ void k_pre2(const float* __restrict__ logp_u, const float* __restrict__ tau) {
    if (blockIdx.x < 16) {
        int row = blockIdx.x * 256 + threadIdx.x;
        const float* r = logp_u + row * AA;
        float m = -3.402823466e38f;
#pragma unroll
        for (int k = 0; k < AA; k++) m = fmaxf(m, r[k]);
        float e[AA], s = 0.f;
#pragma unroll
        for (int k = 0; k < AA; k++) { e[k] = expf(r[k] - m); s += e[k]; }
        float inv = 1.0f / s;
        float* o = d_alpha_a + row * AA;
#pragma unroll
        for (int k = 0; k < AA; k++) o[k] = e[k] * inv;
    } else if (threadIdx.x < HH) {
        int h = threadIdx.x;
        float rate = log1pf(expf(tau[0]));
        float lp = (float)(h + 1) * logf(rate) - rate - lgammaf((float)(h + 2));
        float p = expf(lp);
        float s = p;
#pragma unroll
        for (int o = 16; o; o >>= 1) s += __shfl_xor_sync(0xffffffffu, s, o);
        d_taupdf[h] = p / s;
    }
}

// ---------------- transition softmax ----------------
__global__ void k_trans() {
    __shared__ float buf[16];
    int ki = blockIdx.x;
    int k = ki >> 9, i = ki & 511;
    int j = threadIdx.x;
    float pki = d_p[k * SS + i];
    float w = d_G[i * SS + j] - 2.0f * pki * d_p[k * SS + j];
    float m = bmaxN(w, buf, 16);
    float e = __expf(w - m);
    float s = bsumN(e, buf, 16);
    d_T[(size_t)ki * SS + j] = e / s;
}

// ---------------- transpose + fp16: Tt[j][k*512+i] = T[k][i][j] ----------------
__global__ void k_tpose() {
    __shared__ float tile[64][65];
    int jb = blockIdx.x, it = blockIdx.y, k = blockIdx.z;
    int tid = threadIdx.x;
#pragma unroll
    for (int l = 0; l < 16; l++) {
        int idx = l * 256 + tid;
        int r = idx >> 6, c = idx & 63;
        tile[r][c] = d_T[((size_t)(k * SS + it * 64 + r)) * SS + jb * 64 + c];
    }
    __syncthreads();
#pragma unroll
    for (int l = 0; l < 16; l++) {
        int idx = l * 256 + tid;
        int r = idx >> 6, c = idx & 63;
        d_Tt[(size_t)(jb * 64 + r) * KI + k * SS + it * 64 + c] = __float2half_rn(tile[c][r]);
    }
}

// ---------------- Ã for t=0 + barrier counter reset ----------------
__global__ void k_abel0(const float* __restrict__ b) {
    __shared__ float a_s[AA];
    if (blockIdx.x == 0 && threadIdx.x == 0) g_cnt = 0u;
    int n = blockIdx.x, j = threadIdx.x;
    if (j < AA) a_s[j] = d_alpha_a[n * AA + j];
    __syncthreads();
    float bel = b[n * SS + j];
#pragma unroll
    for (int k = 0; k < AA; k++)
        d_ab[(size_t)n * KI + k * SS + j] = __float2half_rn(a_s[k] * bel);
}

// ---------------- persistent scan: 64 x (HMMA GEMM + bar + post + bar) ----------------
// grid (4 jt, 32 ks) = 128 CTAs (one wave), 256 threads, 1 CTA/SM.
// A (Tt fp16, 128j x 256ki) preloaded ONCE into REGISTERS (64/lane) via a smem stage.
// Per step: load B = ab slice (fp16, 64n x 256ki) -> smem, single fp16 GEMM,
// write split-K partials, bar, CTAs 0..63 posterior softmax + produce ab(t+1), bar.
#define S_A 0
#define S_B 65536
#define S_PB 98304
#define SCAN_SMEM (98304 + 256)

__global__ __launch_bounds__(256, 1) void k_scan(const float* __restrict__ logp_o,
                                                 float* __restrict__ alpha_b) {
    extern __shared__ __align__(128) char sm[];
    uint32_t sb = smem_u32(sm);
    float* buf = (float*)(sm + S_PB);
    float* a_s = buf + 16;
    int tid = threadIdx.x, w = tid >> 5, lane = tid & 31;
    int jt = blockIdx.x, ks = blockIdx.y;
    int cta = ks * 4 + jt;
    int j0 = jt * 128, ki0 = ks * 256;

    int r8 = lane & 7, sub = lane >> 3;
    int arow = 16 * w + r8 + ((sub & 1) << 3);
    uint32_t a_off = (uint32_t)(arow * 512);
    int acol16 = (sub & 2) << 3;
    uint32_t axor = (uint32_t)(r8 << 4);
    int bcol16 = (sub & 1) << 4;
    int brow_base = ((sub >> 1) << 3) + r8;
    int jl = 16 * w + (lane >> 2);
    int nb = 2 * (lane & 3);

    // ---- stage A into smem (swizzled), then preload fragments into registers ----
    {
        const uint4* gA = (const uint4*)d_Tt;
#pragma unroll
        for (int l = 0; l < 16; l++) {
            int idx = l * 256 + tid;
            int r = idx >> 5, c = idx & 31;
            size_t gi = (size_t)(j0 + r) * (KI / 8) + (ki0 >> 3) + c;
            uint32_t so = (uint32_t)(r * 512 + ((c * 16) ^ ((r & 7) << 4)));
            *(uint4*)(sm + S_A + so) = gA[gi];
        }
    }
    __syncthreads();
    uint32_t areg[16][4];
#pragma unroll
    for (int s = 0; s < 16; s++) {
        uint32_t ac = ((uint32_t)(32 * s + acol16)) ^ axor;
        ldsm_x4(areg[s], sb + S_A + a_off + ac);
    }

    unsigned bar = 0;

    for (int t = 0; t < TT; t++) {
        // ---- B load (written by post on other SMs -> bypass L1 via ldcg) ----
        {
            const uint4* gB = (const uint4*)d_ab;
#pragma unroll
            for (int l = 0; l < 8; l++) {
                int idx = l * 256 + tid;
                int rr = idx >> 5, c = idx & 31;
                uint4 vb = __ldcg(&gB[(size_t)rr * (KI / 8) + (ki0 >> 3) + c]);
                uint32_t so = (uint32_t)(rr * 512 + ((c * 16) ^ ((rr & 7) << 4)));
                *(uint4*)(sm + S_B + so) = vb;
            }
        }
        __syncthreads();

        // ---- single fp16 GEMM: warp w covers j [16w,16w+16), all 64 n ----
        float acc[8][4];
#pragma unroll
        for (int tt = 0; tt < 8; tt++)
#pragma unroll
            for (int q = 0; q < 4; q++) acc[tt][q] = 0.f;

#pragma unroll 4
        for (int s = 0; s < 16; s++) {
            uint32_t bh[16];
            uint32_t bc = ((uint32_t)(32 * s + bcol16)) ^ axor;
#pragma unroll
            for (int q = 0; q < 4; q++) {
                uint32_t bo = (uint32_t)((16 * q + brow_base) * 512) + bc;
                ldsm_x4(bh + 4 * q, sb + S_B + bo);
            }
#pragma unroll
            for (int tt = 0; tt < 8; tt++) {
                int base = 4 * (tt >> 1) + (tt & 1) * 2;
                mma_f16(acc[tt], areg[s], bh[base], bh[base + 1]);
            }
        }
        // ---- epilogue: split-K partials ----
#pragma unroll
        for (int tt = 0; tt < 8; tt++) {
            int n = 8 * tt + nb;
            float* p0 = &d_partial[((size_t)ks * BB + n) * SS + j0 + jl];
            p0[0] = acc[tt][0];
            p0[SS] = acc[tt][1];
            p0[8] = acc[tt][2];
            p0[SS + 8] = acc[tt][3];
        }
        __syncthreads();  // protect smem B until all warps done (next fill overwrites)

        grid_bar(++bar * 128u);

        // ---- post: CTAs 0..63, n = cta; thread handles j = tid and tid+256 ----
        if (cta < 64) {
            int n = cta;
            if (tid < AA && t + 1 < TT)
                a_s[tid] = d_alpha_a[(size_t)(t + 1) * BB * AA + n * AA + tid];
            float s0 = 0.f, s1 = 0.f;
#pragma unroll
            for (int c = 0; c < 32; c++) {
                const float* pp = &d_partial[((size_t)c * BB + n) * SS];
                s0 += __ldcg(pp + tid);
                s1 += __ldcg(pp + tid + 256);
            }
            const float* lo = logp_o + (size_t)t * BB * SS + (size_t)n * SS;
            float v0 = __logf(s0 + EPSV) + lo[tid];
            float v1 = __logf(s1 + EPSV) + lo[tid + 256];
            float m = bmaxN(fmaxf(v0, v1), buf, 8);
            float e0 = __expf(v0 - m), e1 = __expf(v1 - m);
            float sum = bsumN(e0 + e1, buf, 8);
            float inv = 1.0f / sum;
            float b0 = e0 * inv, b1 = e1 * inv;
            float* abp = alpha_b + (size_t)t * BB * SS + (size_t)n * SS;
            abp[tid] = b0;
            abp[tid + 256] = b1;
            if (t + 1 < TT) {
#pragma unroll
                for (int k = 0; k < AA; k++) {
                    float ak = a_s[k];
                    d_ab[(size_t)n * KI + k * SS + tid] = __float2half_rn(ak * b0);
                    d_ab[(size_t)n * KI + k * SS + tid + 256] = __float2half_rn(ak * b1);
                }
            }
        }
        grid_bar(++bar * 128u);
    }
}

// ---------------- batched plan (outside the sequential chain) ----------------
#define PLAN_SMEM (3 * 64 * 68 * 4)
__global__ __launch_bounds__(256, 4) void k_plan(const float* __restrict__ alpha_b,
                                                 const float* __restrict__ value) {
    extern __shared__ char sm[];
    float(*Vs)[68] = (float(*)[68])sm;
    float(*Bs)[68] = (float(*)[68])(sm + 64 * 68 * 4);
    float(*lg)[68] = (float(*)[68])(sm + 2 * 64 * 68 * 4);

    int n = blockIdx.x, hs = blockIdx.y;
    int h0 = hs * 4;
    int tid = threadIdx.x;
    int tx = tid & 15;
    int ty = tid >> 4;

    unsigned long long acc[4][2];
#pragma unroll
    for (int a = 0; a < 4; a++) { acc[a][0] = 0ull; acc[a][1] = 0ull; }

    for (int c = 0; c < 8; c++) {
        int i0 = c * 64;
#pragma unroll
        for (int l = 0; l < 4; l++) {
            int idx = l * 256 + tid;
            int ii = idx & 63, r4 = idx >> 6;
            float4 vv;
#pragma unroll
            for (int q = 0; q < 4; q++) {
                int row = r4 * 4 + q;
                int hh = row >> 4, kk = row & 15;
                ((float*)&vv)[q] = value[(((size_t)(h0 + hh) * BB + n) * AA + kk) * SS + i0 + ii];
            }
            *(float4*)&Vs[ii][r4 * 4] = vv;
        }
#pragma unroll
        for (int l = 0; l < 4; l++) {
            int idx = l * 256 + tid;
            int ii = idx & 63, t4 = idx >> 6;
            float4 bv;
            bv.x = alpha_b[((size_t)(t4 * 4 + 0) * BB + n) * SS + i0 + ii];
            bv.y = alpha_b[((size_t)(t4 * 4 + 1) * BB + n) * SS + i0 + ii];
            bv.z = alpha_b[((size_t)(t4 * 4 + 2) * BB + n) * SS + i0 + ii];
            bv.w = alpha_b[((size_t)(t4 * 4 + 3) * BB + n) * SS + i0 + ii];
            *(float4*)&Bs[ii][t4 * 4] = bv;
        }
        __syncthreads();
#pragma unroll 8
        for (int ii = 0; ii < 64; ii++) {
            ulonglong2 vv = *(const ulonglong2*)&Vs[ii][tx * 4];
            float4 bv = *(const float4*)&Bs[ii][ty * 4];
            unsigned long long b0 = pack2(bv.x), b1 = pack2(bv.y),
                               b2 = pack2(bv.z), b3 = pack2(bv.w);
            fma2(acc[0][0], b0, vv.x); fma2(acc[0][1], b0, vv.y);
            fma2(acc[1][0], b1, vv.x); fma2(acc[1][1], b1, vv.y);
            fma2(acc[2][0], b2, vv.x); fma2(acc[2][1], b2, vv.y);
            fma2(acc[3][0], b3, vv.x); fma2(acc[3][1], b3, vv.y);
        }
        __syncthreads();
    }
#pragma unroll
    for (int tt = 0; tt < 4; tt++) {
        int t = ty * 4 + tt;
        float2 f0 = *(float2*)&acc[tt][0];
        float2 f1 = *(float2*)&acc[tt][1];
        lg[t][tx * 4] = f0.x;
        lg[t][tx * 4 + 1] = f0.y;
        lg[t][tx * 4 + 2] = f1.x;
        lg[t][tx * 4 + 3] = f1.y;
    }
    __syncthreads();
    {
        int t = tid >> 2, hh = tid & 3;
        const float* row = &lg[t][hh * 16];
        float mm = -3.402823466e38f;
#pragma unroll
        for (int k = 0; k < AA; k++) mm = fmaxf(mm, row[k]);
        float ex[AA], se = 0.f;
#pragma unroll
        for (int k = 0; k < AA; k++) { ex[k] = __expf(row[k] - mm); se += ex[k]; }
        float tw = d_taupdf[h0 + hh] / se;
        float pv[AA];
#pragma unroll
        for (int k = 0; k < AA; k++) pv[k] = ex[k] * tw;
#pragma unroll
        for (int k = 0; k < AA; k++) {
            pv[k] += __shfl_xor_sync(0xffffffffu, pv[k], 1);
            pv[k] += __shfl_xor_sync(0xffffffffu, pv[k], 2);
        }
        float* op = &d_pi_part[(((size_t)hs * TT + t) * BB + n) * AA];
#pragma unroll
        for (int q = 0; q < 4; q++) op[hh * 4 + q] = pv[hh * 4 + q];
    }
}

__global__ void k_pisum(float* __restrict__ api) {
    int idx = blockIdx.x * 256 + threadIdx.x;
    float s = 0.f;
#pragma unroll
    for (int hs = 0; hs < 8; hs++) s += d_pi_part[(size_t)hs * TT * BB * AA + idx];
    api[idx] = s;
}

// ---------------- launch ----------------
extern "C" void kernel_launch(void* const* d_in, const int* in_sizes, int n_in,
                              void* d_out, int out_size) {
    const float* logp_o = (const float*)d_in[0];
    const float* logp_u = (const float*)d_in[1];
    const float* value  = (const float*)d_in[2];
    const float* b      = (const float*)d_in[3];
    const float* u      = (const float*)d_in[4];
    const float* v      = (const float*)d_in[5];
    const float* tau    = (const float*)d_in[6];

    float* out = (float*)d_out;
    float* alpha_b  = out;                         // [T,B,S]
    float* alpha_pi = out + (size_t)TT * BB * SS;  // [T,B,A]

    cudaFuncSetAttribute(k_scan, cudaFuncAttributeMaxDynamicSharedMemorySize, SCAN_SMEM);
    cudaFuncSetAttribute(k_plan, cudaFuncAttributeMaxDynamicSharedMemorySize, PLAN_SMEM);

    k_pre1<<<528, 512>>>(u, v);
    k_pre2<<<17, 256>>>(logp_u, tau);
    k_trans<<<AA * SS, 512>>>();
    {
        dim3 gt(8, 8, 16);
        k_tpose<<<gt, 256>>>();
    }
    k_abel0<<<BB, 512>>>(b);

    {
        dim3 gs(4, 32);
        k_scan<<<gs, 256, SCAN_SMEM>>>(logp_o, alpha_b);
    }

    dim3 gp(BB, 8);
    k_plan<<<gp, 256, PLAN_SMEM>>>(alpha_b, value);
    k_pisum<<<256, 256>>>(alpha_pi);
}